// round 5
// baseline (speedup 1.0000x reference)
#include <cuda_runtime.h>
#include <cuda_fp16.h>
#include <math.h>
#include <stdint.h>

#define NPIX   65536
#define HW     4096

#define Q_OFF    1
#define NV_OFF   8388609
#define PERP_OFF 16777217
#define IDX_OFF  16777218

// ---------------- scratch (static device arrays; no allocations) ----------------
__device__ float g_xT[128 * NPIX];       // conv1 output, transposed [d][p] (32 MB)
__device__ float g_eT[128 * 1024];       // emb transposed [d][k]
__device__ float g_enorm[1024];          // ||e_k||^2
__device__ float g_w1t[128 * 128];
__device__ float g_w2t[128 * 1152];
__device__ float g_U[1024 * 1152];
__device__ int   g_idx[NPIX];
__device__ int   g_counts[1024];
__device__ float g_lpart[1024];
__device__ float g_xnorm[NPIX];
__device__ float g_emax;
__device__ int   g_fbcount;              // full-fallback pixels
__device__ int   g_fblist[NPIX];
__device__ int   g_fbcount2;             // pair-fix pixels
__device__ int   g_fbp2[NPIX];
__device__ int   g_fbc2[NPIX];
__device__ __align__(16) __half g_x16[NPIX * 128];   // x fp16, row-major [p][d]
__device__ __align__(16) __half g_e16[1024 * 128];   // e fp16, row-major [k][d]

// ---------------- warp MMA helpers (baseline PTX, sm_80+) ----------------
__device__ __forceinline__ uint32_t smem_to_u32(const void* p) {
    uint32_t a;
    asm("{ .reg .u64 t; cvta.to.shared.u64 t, %1; cvt.u32.u64 %0, t; }" : "=r"(a) : "l"(p));
    return a;
}
__device__ __forceinline__ void ldsm_x4(uint32_t& r0, uint32_t& r1, uint32_t& r2, uint32_t& r3, uint32_t addr) {
    asm volatile("ldmatrix.sync.aligned.m8n8.x4.shared.b16 {%0,%1,%2,%3}, [%4];"
                 : "=r"(r0), "=r"(r1), "=r"(r2), "=r"(r3) : "r"(addr));
}
__device__ __forceinline__ void ldsm_x2(uint32_t& r0, uint32_t& r1, uint32_t addr) {
    asm volatile("ldmatrix.sync.aligned.m8n8.x2.shared.b16 {%0,%1}, [%2];"
                 : "=r"(r0), "=r"(r1) : "r"(addr));
}
__device__ __forceinline__ void mma16816(float* c, const uint32_t* a, const uint32_t* b) {
    asm volatile("mma.sync.aligned.m16n8k16.row.col.f32.f16.f16.f32 "
                 "{%0,%1,%2,%3}, {%4,%5,%6,%7}, {%8,%9}, {%0,%1,%2,%3};"
                 : "+f"(c[0]), "+f"(c[1]), "+f"(c[2]), "+f"(c[3])
                 : "r"(a[0]), "r"(a[1]), "r"(a[2]), "r"(a[3]), "r"(b[0]), "r"(b[1]));
}

// merge two sorted top-3 sets: (a1,ai1)<=(a2,ai2)<=a3 with b-set; result in a.
// index-aware compare on slot-1 (first-occurrence argmin semantics).
__device__ __forceinline__ void merge3(float& a1, int& ai1, float& a2, int& ai2, float& a3,
                                       float b1, int bi1, float b2, int bi2, float b3) {
    if (b1 < a1 || (b1 == a1 && bi1 < ai1)) {
        float t; int ti;
        t = a1; a1 = b1; b1 = t; ti = ai1; ai1 = bi1; bi1 = ti;
        t = a2; a2 = b2; b2 = t; ti = ai2; ai2 = bi2; bi2 = ti;
        t = a3; a3 = b3; b3 = t;
    }
    if (b1 < a2 || (b1 == a2 && bi1 < ai2)) {
        a3 = fminf(a2, b2);
        a2 = b1; ai2 = bi1;
    } else {
        a3 = fminf(a3, b1);
    }
}

// ---------------- prep ----------------
__global__ void prep_kernel(const float* __restrict__ emb,
                            const float* __restrict__ w1,
                            const float* __restrict__ w2) {
    int t = blockIdx.x * blockDim.x + threadIdx.x;
    if (t < 131072) {
        int k = t >> 7, d = t & 127;
        float v = emb[t];
        g_eT[d * 1024 + k] = v;
        g_e16[t] = __float2half_rn(v);
    }
    if (t < 16384)  { int d = t >> 7, c = t & 127; g_w1t[c * 128 + d] = w1[t]; }
    if (t < 147456) {
        int o = t / 1152; int r = t - o * 1152; int i = r / 9, j = r - i * 9;
        g_w2t[i * 1152 + j * 128 + o] = w2[t];
    }
    if (t < 1024) {
        const float* e = emb + t * 128;
        float s = 0.f;
        for (int d = 0; d < 128; d++) s = fmaf(e[d], e[d], s);
        g_enorm[t] = s;
        g_counts[t] = 0;
    }
}

__global__ void prep2_kernel() {
    __shared__ float mx[256];
    const int t = threadIdx.x;
    float m = 0.f;
    for (int k = t; k < 1024; k += 256) m = fmaxf(m, g_enorm[k]);
    mx[t] = m;
    __syncthreads();
    for (int off = 128; off > 0; off >>= 1) {
        if (t < off) mx[t] = fmaxf(mx[t], mx[t + off]);
        __syncthreads();
    }
    if (t == 0) { g_emax = sqrtf(mx[0]); g_fbcount = 0; g_fbcount2 = 0; }
}

// ---------------- conv1: SGEMM + fused fp16 conversion + per-pixel norms ----------------
__global__ __launch_bounds__(256) void conv1_kernel(const float* __restrict__ in,
                                                    const float* __restrict__ bias) {
    __shared__ float as[16 * 128];
    __shared__ float bs[16 * 128];
    __shared__ float pn[128][17];
    const int tid = threadIdx.x;
    const int b   = blockIdx.y;
    const int hwb = blockIdx.x * 128;
    const int m0  = (tid >> 4) * 8;
    const int n0  = (tid & 15) * 8;
    const int lr  = tid >> 4;
    const int lc  = (tid & 15) * 8;
    const float* B = in + b * (128 * HW);

    float acc[8][8];
#pragma unroll
    for (int i = 0; i < 8; i++)
#pragma unroll
        for (int j = 0; j < 8; j++) acc[i][j] = 0.f;

    for (int ks = 0; ks < 8; ks++) {
        const int c0 = ks * 16 + lr;
        __syncthreads();
        *(float4*)&as[lr * 128 + lc]     = *(const float4*)&g_w1t[c0 * 128 + lc];
        *(float4*)&as[lr * 128 + lc + 4] = *(const float4*)&g_w1t[c0 * 128 + lc + 4];
        *(float4*)&bs[lr * 128 + lc]     = *(const float4*)&B[c0 * HW + hwb + lc];
        *(float4*)&bs[lr * 128 + lc + 4] = *(const float4*)&B[c0 * HW + hwb + lc + 4];
        __syncthreads();
#pragma unroll
        for (int kk = 0; kk < 16; kk++) {
            float4 a0 = *(float4*)&as[kk * 128 + m0];
            float4 a1 = *(float4*)&as[kk * 128 + m0 + 4];
            float4 b0 = *(float4*)&bs[kk * 128 + n0];
            float4 b1 = *(float4*)&bs[kk * 128 + n0 + 4];
            float a[8] = {a0.x, a0.y, a0.z, a0.w, a1.x, a1.y, a1.z, a1.w};
            float bb[8] = {b0.x, b0.y, b0.z, b0.w, b1.x, b1.y, b1.z, b1.w};
#pragma unroll
            for (int i = 0; i < 8; i++)
#pragma unroll
                for (int j = 0; j < 8; j++) acc[i][j] = fmaf(a[i], bb[j], acc[i][j]);
        }
    }
#pragma unroll
    for (int i = 0; i < 8; i++) {
        const float bv = bias[m0 + i];
#pragma unroll
        for (int j = 0; j < 8; j++) acc[i][j] += bv;
    }
#pragma unroll
    for (int i = 0; i < 8; i++) {
        float4 v0, v1;
        v0.x = acc[i][0]; v0.y = acc[i][1]; v0.z = acc[i][2]; v0.w = acc[i][3];
        v1.x = acc[i][4]; v1.y = acc[i][5]; v1.z = acc[i][6]; v1.w = acc[i][7];
        float* dst = &g_xT[(size_t)(m0 + i) * NPIX + b * HW + hwb + n0];
        *(float4*)dst = v0;
        *(float4*)(dst + 4) = v1;
    }
#pragma unroll
    for (int j = 0; j < 8; j++) {
        const int p = b * HW + hwb + n0 + j;
        __half h[8];
#pragma unroll
        for (int i = 0; i < 8; i++) h[i] = __float2half_rn(acc[i][j]);
        *(uint4*)&g_x16[(size_t)p * 128 + m0] = *(uint4*)h;
    }
#pragma unroll
    for (int j = 0; j < 8; j++) {
        float s = 0.f;
#pragma unroll
        for (int i = 0; i < 8; i++) s = fmaf(acc[i][j], acc[i][j], s);
        pn[n0 + j][tid >> 4] = s;
    }
    __syncthreads();
    if (tid < 128) {
        float s = 0.f;
#pragma unroll
        for (int g = 0; g < 16; g++) s += pn[tid][g];
        g_xnorm[b * HW + hwb + tid] = sqrtf(s);
    }
}

// ---------------- U precompute GEMM ----------------
__global__ __launch_bounds__(256) void ugemm_kernel() {
    __shared__ float as[16 * 128];
    __shared__ float bs[16 * 128];
    const int tid = threadIdx.x;
    const int mb = blockIdx.y * 128;
    const int nb = blockIdx.x * 128;
    const int m0 = (tid >> 4) * 8;
    const int n0 = (tid & 15) * 8;
    const int lr = tid >> 4;
    const int lc = (tid & 15) * 8;

    float acc[8][8];
#pragma unroll
    for (int i = 0; i < 8; i++)
#pragma unroll
        for (int j = 0; j < 8; j++) acc[i][j] = 0.f;

    for (int ks = 0; ks < 8; ks++) {
        const int r = ks * 16 + lr;
        __syncthreads();
        *(float4*)&as[lr * 128 + lc]     = *(const float4*)&g_eT[r * 1024 + mb + lc];
        *(float4*)&as[lr * 128 + lc + 4] = *(const float4*)&g_eT[r * 1024 + mb + lc + 4];
        *(float4*)&bs[lr * 128 + lc]     = *(const float4*)&g_w2t[r * 1152 + nb + lc];
        *(float4*)&bs[lr * 128 + lc + 4] = *(const float4*)&g_w2t[r * 1152 + nb + lc + 4];
        __syncthreads();
#pragma unroll
        for (int kk = 0; kk < 16; kk++) {
            float4 a0 = *(float4*)&as[kk * 128 + m0];
            float4 a1 = *(float4*)&as[kk * 128 + m0 + 4];
            float4 b0 = *(float4*)&bs[kk * 128 + n0];
            float4 b1 = *(float4*)&bs[kk * 128 + n0 + 4];
            float a[8] = {a0.x, a0.y, a0.z, a0.w, a1.x, a1.y, a1.z, a1.w};
            float bb[8] = {b0.x, b0.y, b0.z, b0.w, b1.x, b1.y, b1.z, b1.w};
#pragma unroll
            for (int i = 0; i < 8; i++)
#pragma unroll
                for (int j = 0; j < 8; j++) acc[i][j] = fmaf(a[i], bb[j], acc[i][j]);
        }
    }
#pragma unroll
    for (int i = 0; i < 8; i++) {
        float4 v0, v1;
        v0.x = acc[i][0]; v0.y = acc[i][1]; v0.z = acc[i][2]; v0.w = acc[i][3];
        v1.x = acc[i][4]; v1.y = acc[i][5]; v1.z = acc[i][6]; v1.w = acc[i][7];
        float* dst = &g_U[(size_t)(mb + m0 + i) * 1152 + nb + n0];
        *(float4*)dst = v0;
        *(float4*)(dst + 4) = v1;
    }
}

// ---------------- screen: fp16 mma.sync distance GEMM + top-3 margin ----------------
#define PITCH  136
#define ES0    34816
#define ES1    69632
#define EN_OFF 104448
#define SCREEN_SMEM 108544

__global__ __launch_bounds__(512, 1) void screen_kernel() {
    extern __shared__ char smc[];
    const uint32_t smb = smem_to_u32(smc);
    const int tid = threadIdx.x;
    const int lane = tid & 31, wid = tid >> 5;
    const int wm = wid >> 3, wn = wid & 7;     // 2 x 8 warp grid; warp tile 64 x 16
    const int pbase = blockIdx.x * 128;

#pragma unroll
    for (int j = 0; j < 4; j++) {
        const int id = j * 512 + tid, r = id >> 4, c = id & 15;
        *(uint4*)(smc + (r * PITCH + c * 8) * 2) =
            *(const uint4*)((const char*)g_x16 + (size_t)(pbase + r) * 256 + c * 16);
    }
#pragma unroll
    for (int j = 0; j < 4; j++) {
        const int id = j * 512 + tid, r = id >> 4, c = id & 15;
        *(uint4*)(smc + ES0 + (r * PITCH + c * 8) * 2) =
            *(const uint4*)((const char*)g_e16 + (size_t)r * 256 + c * 16);
    }
    if (tid < 256) *(float4*)(smc + EN_OFF + tid * 16) = *(const float4*)&g_enorm[tid * 4];
    __syncthreads();

    const float* ensm = (const float*)(smc + EN_OFF);
    float mn1[8], mn2[8], mn3[8]; int mi1[8], mi2[8];
#pragma unroll
    for (int s = 0; s < 8; s++) { mn1[s] = 3.4e38f; mn2[s] = 3.4e38f; mn3[s] = 3.4e38f; mi1[s] = 0; mi2[s] = 0; }

    const uint32_t a_row = (uint32_t)(wm * 64 + (lane & 15));
    const uint32_t a_koff = (uint32_t)((lane >> 4) << 3);
    const uint32_t b_row = (uint32_t)(wn * 16 + (lane & 7));
    const uint32_t b_koff = (uint32_t)(((lane >> 3) & 1) << 3);

    for (int nt = 0; nt < 8; nt++) {
        const int ebase = (nt & 1) ? ES1 : ES0;
        float acc[4][2][4];
#pragma unroll
        for (int mt = 0; mt < 4; mt++)
#pragma unroll
            for (int ntl = 0; ntl < 2; ntl++)
#pragma unroll
                for (int c = 0; c < 4; c++) acc[mt][ntl][c] = 0.f;

        if (nt < 7) {
            const char* src = (const char*)g_e16 + (size_t)(nt + 1) * 128 * 256;
            char* dst = smc + ((nt & 1) ? ES0 : ES1);
#pragma unroll
            for (int j = 0; j < 4; j++) {
                const int id = j * 512 + tid, r = id >> 4, c = id & 15;
                *(uint4*)(dst + (r * PITCH + c * 8) * 2) = *(const uint4*)(src + r * 256 + c * 16);
            }
        }
#pragma unroll
        for (int kk = 0; kk < 8; kk++) {
            uint32_t a[4][4];
#pragma unroll
            for (int mt = 0; mt < 4; mt++) {
                const uint32_t addr = smb + ((a_row + mt * 16) * PITCH + kk * 16 + a_koff) * 2;
                ldsm_x4(a[mt][0], a[mt][1], a[mt][2], a[mt][3], addr);
            }
            uint32_t b[2][2];
#pragma unroll
            for (int ntl = 0; ntl < 2; ntl++) {
                const uint32_t addr = smb + ebase + ((b_row + ntl * 8) * PITCH + kk * 16 + b_koff) * 2;
                ldsm_x2(b[ntl][0], b[ntl][1], addr);
            }
#pragma unroll
            for (int mt = 0; mt < 4; mt++)
#pragma unroll
                for (int ntl = 0; ntl < 2; ntl++) mma16816(acc[mt][ntl], a[mt], b[ntl]);
        }
        // top-3 update (cols ascending per thread -> first-min tie semantics)
#pragma unroll
        for (int mt = 0; mt < 4; mt++)
#pragma unroll
            for (int c = 0; c < 4; c++) {
                const int slot = mt * 2 + (c >> 1);
#pragma unroll
                for (int ntl = 0; ntl < 2; ntl++) {
                    const int col = nt * 128 + wn * 16 + ntl * 8 + ((lane & 3) << 1) + (c & 1);
                    const float s = fmaf(-2.f, acc[mt][ntl][c], ensm[col]);
                    if (s < mn1[slot]) {
                        mn3[slot] = mn2[slot]; mn2[slot] = mn1[slot]; mi2[slot] = mi1[slot];
                        mn1[slot] = s; mi1[slot] = col;
                    } else if (s < mn2[slot]) {
                        mn3[slot] = mn2[slot]; mn2[slot] = s; mi2[slot] = col;
                    } else if (s < mn3[slot]) {
                        mn3[slot] = s;
                    }
                }
            }
        __syncthreads();
    }

    // in-warp merge across the 4 lanes sharing each row
#pragma unroll
    for (int s = 0; s < 8; s++) {
#pragma unroll
        for (int m = 1; m <= 2; m <<= 1) {
            const float o1 = __shfl_xor_sync(0xffffffffu, mn1[s], m);
            const int   oi1 = __shfl_xor_sync(0xffffffffu, mi1[s], m);
            const float o2 = __shfl_xor_sync(0xffffffffu, mn2[s], m);
            const int   oi2 = __shfl_xor_sync(0xffffffffu, mi2[s], m);
            const float o3 = __shfl_xor_sync(0xffffffffu, mn3[s], m);
            merge3(mn1[s], mi1[s], mn2[s], mi2[s], mn3[s], o1, oi1, o2, oi2, o3);
        }
    }
    // cross-warp merge via smem (xs region dead: 20 KB < 34 KB)
    float* f1 = (float*)smc;
    int*   j1 = (int*)(smc + 4096);
    float* f2 = (float*)(smc + 8192);
    int*   j2 = (int*)(smc + 12288);
    float* f3 = (float*)(smc + 16384);
    if ((lane & 3) == 0) {
#pragma unroll
        for (int s = 0; s < 8; s++) {
            const int row = wm * 64 + (s >> 1) * 16 + (s & 1) * 8 + (lane >> 2);
            f1[row * 8 + wn] = mn1[s]; j1[row * 8 + wn] = mi1[s];
            f2[row * 8 + wn] = mn2[s]; j2[row * 8 + wn] = mi2[s];
            f3[row * 8 + wn] = mn3[s];
        }
    }
    __syncthreads();
    if (tid < 128) {
        float m1 = f1[tid * 8], m2 = f2[tid * 8], m3 = f3[tid * 8];
        int i1 = j1[tid * 8], i2 = j2[tid * 8];
#pragma unroll
        for (int w = 1; w < 8; w++) {
            merge3(m1, i1, m2, i2, m3,
                   f1[tid * 8 + w], j1[tid * 8 + w], f2[tid * 8 + w], j2[tid * 8 + w], f3[tid * 8 + w]);
        }
        const int p = pbase + tid;
        g_idx[p] = i1;
        const float thresh = fmaf(4.5e-3f * g_emax, g_xnorm[p], 1e-5f);
        if (m3 - m1 <= thresh) {
            const int pos = atomicAdd(&g_fbcount, 1);   // rare: full rescore
            g_fblist[pos] = p;
        } else if (m2 - m1 <= thresh) {
            const int pos = atomicAdd(&g_fbcount2, 1);  // common: pair rescore
            g_fbp2[pos] = p;
            g_fbc2[pos] = i2;
        }
    }
}

// ---------------- pairfix: exact fp32 rescore of {i1, i2} per flagged pixel ----------------
__global__ __launch_bounds__(256) void pairfix_kernel(const float* __restrict__ emb) {
    const int cnt = g_fbcount2;
    const int gw = (blockIdx.x * blockDim.x + threadIdx.x) >> 5;
    const int lane = threadIdx.x & 31;
    const int nw = (gridDim.x * blockDim.x) >> 5;
    for (int wi = gw; wi < cnt; wi += nw) {
        const int p = g_fbp2[wi];
        const int c2 = g_fbc2[wi];
        const int c1 = g_idx[p];
        float dot1 = 0.f, dot2 = 0.f;
#pragma unroll
        for (int j = 0; j < 4; j++) {
            const int d = lane + j * 32;
            const float xv = g_xT[(size_t)d * NPIX + p];
            dot1 = fmaf(xv, emb[c1 * 128 + d], dot1);
            dot2 = fmaf(xv, emb[c2 * 128 + d], dot2);
        }
#pragma unroll
        for (int off = 16; off > 0; off >>= 1) {
            dot1 += __shfl_down_sync(0xffffffffu, dot1, off);
            dot2 += __shfl_down_sync(0xffffffffu, dot2, off);
        }
        if (lane == 0) {
            const float d1 = fmaf(-2.f, dot1, g_enorm[c1]);
            const float d2 = fmaf(-2.f, dot2, g_enorm[c2]);
            g_idx[p] = (d2 < d1 || (d2 == d1 && c2 < c1)) ? c2 : c1;
        }
    }
}

// ---------------- full fallback: exact fp32 SGEMM-argmin over rare pixels ----------------
__global__ __launch_bounds__(256) void fb_kernel() {
    extern __shared__ float sm[];
    float* xs = sm;
    float* bs = sm + 16384;
    int*   pl = (int*)(sm + 18432);
    unsigned long long* red = (unsigned long long*)sm;

    const int tid = threadIdx.x;
    const int cnt = g_fbcount;
    const int ntiles = (cnt + 127) >> 7;

    for (int t = blockIdx.x; t < ntiles; t += gridDim.x) {
        __syncthreads();
        if (tid < 128) {
            const int li = t * 128 + tid;
            pl[tid] = (li < cnt) ? g_fblist[li] : g_fblist[0];
        }
        __syncthreads();
        {
            const int i = tid & 127;
            const int p = pl[i];
#pragma unroll 4
            for (int j = 0; j < 64; j++) {
                const int d = (tid >> 7) + j * 2;
                xs[d * 128 + i] = g_xT[(size_t)d * NPIX + p];
            }
        }
        __syncthreads();

        const int m0 = (tid >> 4) * 8;
        const int n0 = (tid & 15) * 8;
        const int lr = tid >> 4;
        const int lc = (tid & 15) * 8;

        float minv[8]; int mini[8];
#pragma unroll
        for (int i = 0; i < 8; i++) { minv[i] = 3.4e38f; mini[i] = 0; }

        for (int nt = 0; nt < 8; nt++) {
            const int kb = nt * 128;
            float acc[8][8];
#pragma unroll
            for (int i = 0; i < 8; i++)
#pragma unroll
                for (int j = 0; j < 8; j++) acc[i][j] = 0.f;

            for (int ks = 0; ks < 8; ks++) {
                const int r = ks * 16 + lr;
                __syncthreads();
                *(float4*)&bs[lr * 128 + lc]     = *(const float4*)&g_eT[r * 1024 + kb + lc];
                *(float4*)&bs[lr * 128 + lc + 4] = *(const float4*)&g_eT[r * 1024 + kb + lc + 4];
                __syncthreads();
#pragma unroll
                for (int kk = 0; kk < 16; kk++) {
                    const int dd = ks * 16 + kk;
                    float4 a0 = *(float4*)&xs[dd * 128 + m0];
                    float4 a1 = *(float4*)&xs[dd * 128 + m0 + 4];
                    float4 b0 = *(float4*)&bs[kk * 128 + n0];
                    float4 b1 = *(float4*)&bs[kk * 128 + n0 + 4];
                    float a[8] = {a0.x, a0.y, a0.z, a0.w, a1.x, a1.y, a1.z, a1.w};
                    float bb[8] = {b0.x, b0.y, b0.z, b0.w, b1.x, b1.y, b1.z, b1.w};
#pragma unroll
                    for (int i = 0; i < 8; i++)
#pragma unroll
                        for (int j = 0; j < 8; j++) acc[i][j] = fmaf(a[i], bb[j], acc[i][j]);
                }
            }
#pragma unroll
            for (int j = 0; j < 8; j++) {
                const float en = g_enorm[kb + n0 + j];
#pragma unroll
                for (int i = 0; i < 8; i++) {
                    float s = fmaf(-2.f, acc[i][j], en);
                    if (s < minv[i]) { minv[i] = s; mini[i] = kb + n0 + j; }
                }
            }
        }
        __syncthreads();
#pragma unroll
        for (int i = 0; i < 8; i++) {
            unsigned int fb = __float_as_uint(minv[i]);
            fb = (fb & 0x80000000u) ? ~fb : (fb | 0x80000000u);
            red[(m0 + i) * 16 + (tid & 15)] = ((unsigned long long)fb << 32) | (unsigned int)mini[i];
        }
        __syncthreads();
        if (tid < 128) {
            unsigned long long m = red[tid * 16];
#pragma unroll
            for (int q = 1; q < 16; q++) {
                unsigned long long v = red[tid * 16 + q];
                if (v < m) m = v;
            }
            g_idx[pl[tid]] = (int)(m & 0xffffffffu);
        }
    }
}

// ---------------- gather: quant write, loss partials, counts, idx out ----------------
__global__ __launch_bounds__(256) void gather_kernel(const float* __restrict__ emb,
                                                     float* __restrict__ out) {
    __shared__ float qs[64 * 132];
    __shared__ int sc[64];
    __shared__ float lred[8];
    const int tid = threadIdx.x;
    const int pbase = blockIdx.x * 64;
    const int w = tid >> 5, lane = tid & 31;

#pragma unroll
    for (int it = 0; it < 8; it++) {
        const int pl = w * 8 + it;
        const int c = g_idx[pbase + pl];
        float4 v = *(const float4*)&emb[c * 128 + lane * 4];
        *(float4*)&qs[pl * 132 + lane * 4] = v;
        if (lane == 0) { sc[pl] = c; atomicAdd(&g_counts[c], 1); }
    }
    __syncthreads();

    const int pl = tid & 63, dg = tid >> 6;
    const int p = pbase + pl;
    const int b = p >> 12, hw = p & 4095;
    float lsum = 0.f;
#pragma unroll
    for (int dd = 0; dd < 32; dd++) {
        const int d = dg * 32 + dd;
        const float q = qs[pl * 132 + d];
        const float x = g_xT[(size_t)d * NPIX + p];
        const float df = q - x;
        lsum = fmaf(df, df, lsum);
        out[Q_OFF + b * (128 * HW) + d * HW + hw] = q;
    }
#pragma unroll
    for (int off = 16; off > 0; off >>= 1) lsum += __shfl_down_sync(0xffffffffu, lsum, off);
    if (lane == 0) lred[w] = lsum;
    __syncthreads();
    if (tid == 0) {
        float s = 0.f;
        for (int i = 0; i < 8; i++) s += lred[i];
        g_lpart[blockIdx.x] = s;
    }
    if (tid < 64) out[IDX_OFF + pbase + tid] = (float)sc[tid];
}

// ---------------- conv2 via U table ----------------
__global__ __launch_bounds__(256) void conv2_kernel(const float* __restrict__ bias,
                                                    float* __restrict__ out) {
    __shared__ int nid[3][66];
    const int tid = threadIdx.x;
    const int y = blockIdx.x, b = blockIdx.y;
    if (tid < 198) {
        const int r = tid / 66, xi = tid % 66 - 1;
        const int yy = y + r - 1;
        int v = -1;
        if (yy >= 0 && yy < 64 && xi >= 0 && xi < 64) v = g_idx[b * HW + yy * 64 + xi];
        nid[r][tid % 66] = v;
    }
    __syncthreads();

    const int x = tid & 63, og = tid >> 6;
    const int ob = og * 32;
    float acc[32];
#pragma unroll
    for (int u = 0; u < 32; u++) acc[u] = bias[ob + u];

#pragma unroll
    for (int ky = 0; ky < 3; ky++)
#pragma unroll
        for (int kx = 0; kx < 3; kx++) {
            const int c = nid[ky][x + kx];
            if (c >= 0) {
                const float4* Up = (const float4*)&g_U[(size_t)c * 1152 + (ky * 3 + kx) * 128 + ob];
#pragma unroll
                for (int u4 = 0; u4 < 8; u4++) {
                    float4 v = Up[u4];
                    acc[u4 * 4 + 0] += v.x; acc[u4 * 4 + 1] += v.y;
                    acc[u4 * 4 + 2] += v.z; acc[u4 * 4 + 3] += v.w;
                }
            }
        }
    const int base = NV_OFF + b * (128 * HW) + y * 64 + x;
#pragma unroll
    for (int u = 0; u < 32; u++) out[base + (ob + u) * HW] = acc[u];
}

// ---------------- finalize ----------------
__global__ void finalize_kernel(float* __restrict__ out) {
    __shared__ double ds[256];
    __shared__ float hs[256];
    const int t = threadIdx.x;
    double s = 0.0;
    float h = 0.f;
    for (int k = t; k < 1024; k += 256) {
        s += (double)g_lpart[k];
        const float avg = (float)g_counts[k] * (1.0f / 65536.0f);
        h += avg * logf(avg + 1e-10f);
    }
    ds[t] = s; hs[t] = h;
    __syncthreads();
    for (int off = 128; off > 0; off >>= 1) {
        if (t < off) { ds[t] += ds[t + off]; hs[t] += hs[t + off]; }
        __syncthreads();
    }
    if (t == 0) {
        out[0] = (float)(1.25 * ds[0] / 8388608.0);
        out[PERP_OFF] = expf(-hs[0]);
    }
}

// ---------------- launch ----------------
extern "C" void kernel_launch(void* const* d_in, const int* in_sizes, int n_in,
                              void* d_out, int out_size) {
    const float* in  = (const float*)d_in[0];
    const float* w1  = (const float*)d_in[1];
    const float* b1  = (const float*)d_in[2];
    const float* emb = (const float*)d_in[3];
    const float* w2  = (const float*)d_in[4];
    const float* b2  = (const float*)d_in[5];
    float* out = (float*)d_out;

    cudaFuncSetAttribute(screen_kernel, cudaFuncAttributeMaxDynamicSharedMemorySize, SCREEN_SMEM);
    cudaFuncSetAttribute(fb_kernel, cudaFuncAttributeMaxDynamicSharedMemorySize, 74240);

    prep_kernel<<<576, 256>>>(emb, w1, w2);
    prep2_kernel<<<1, 256>>>();
    conv1_kernel<<<dim3(32, 16), 256>>>(in, b1);
    ugemm_kernel<<<dim3(9, 8), 256>>>();
    screen_kernel<<<512, 512, SCREEN_SMEM>>>();
    pairfix_kernel<<<128, 256>>>(emb);
    fb_kernel<<<64, 256, 74240>>>();
    gather_kernel<<<1024, 256>>>(emb, out);
    conv2_kernel<<<dim3(64, 16), 256>>>(b2, out);
    finalize_kernel<<<1, 256>>>(out);
}

// round 6
// speedup vs baseline: 1.1324x; 1.1324x over previous
#include <cuda_runtime.h>
#include <cuda_fp16.h>
#include <math.h>
#include <stdint.h>

#define NPIX   65536
#define HW     4096

#define Q_OFF    1
#define NV_OFF   8388609
#define PERP_OFF 16777217
#define IDX_OFF  16777218

// ---------------- scratch (static device arrays; no allocations) ----------------
__device__ float g_xT[128 * NPIX];       // conv1 output, transposed [d][p] (32 MB)
__device__ float g_eT[128 * 1024];       // emb transposed [d][k]
__device__ float g_enorm[1024];          // ||e_k||^2
__device__ float g_w1t[128 * 128];
__device__ float g_w2t[128 * 1152];
__device__ float g_U[1024 * 1152];
__device__ int   g_idx[NPIX];
__device__ int   g_counts[1024];
__device__ float g_lpart[1024];
__device__ float g_xnorm[NPIX];
__device__ float g_emax;
__device__ int   g_fbcount;
__device__ int   g_fblist[NPIX];
__device__ float g_sm1[2 * NPIX];        // per-half top-1 score
__device__ int   g_si1[2 * NPIX];        // per-half top-1 col (global)
__device__ float g_sm2[2 * NPIX];        // per-half top-2 score
__device__ __align__(16) __half g_x16[NPIX * 128];   // x fp16, row-major [p][d]
__device__ __align__(16) __half g_e16[1024 * 128];   // e fp16, row-major [k][d]

// ---------------- warp MMA helpers (baseline PTX, sm_80+) ----------------
__device__ __forceinline__ uint32_t smem_to_u32(const void* p) {
    uint32_t a;
    asm("{ .reg .u64 t; cvta.to.shared.u64 t, %1; cvt.u32.u64 %0, t; }" : "=r"(a) : "l"(p));
    return a;
}
__device__ __forceinline__ void ldsm_x4(uint32_t& r0, uint32_t& r1, uint32_t& r2, uint32_t& r3, uint32_t addr) {
    asm volatile("ldmatrix.sync.aligned.m8n8.x4.shared.b16 {%0,%1,%2,%3}, [%4];"
                 : "=r"(r0), "=r"(r1), "=r"(r2), "=r"(r3) : "r"(addr));
}
__device__ __forceinline__ void mma16816(float* c, const uint32_t* a, const uint32_t* b) {
    asm volatile("mma.sync.aligned.m16n8k16.row.col.f32.f16.f16.f32 "
                 "{%0,%1,%2,%3}, {%4,%5,%6,%7}, {%8,%9}, {%0,%1,%2,%3};"
                 : "+f"(c[0]), "+f"(c[1]), "+f"(c[2]), "+f"(c[3])
                 : "r"(a[0]), "r"(a[1]), "r"(a[2]), "r"(a[3]), "r"(b[0]), "r"(b[1]));
}

// ---------------- prep ----------------
__global__ void prep_kernel(const float* __restrict__ emb,
                            const float* __restrict__ w1,
                            const float* __restrict__ w2) {
    int t = blockIdx.x * blockDim.x + threadIdx.x;
    if (t < 131072) {
        int k = t >> 7, d = t & 127;
        float v = emb[t];
        g_eT[d * 1024 + k] = v;
        g_e16[t] = __float2half_rn(v);
    }
    if (t < 16384)  { int d = t >> 7, c = t & 127; g_w1t[c * 128 + d] = w1[t]; }
    if (t < 147456) {
        int o = t / 1152; int r = t - o * 1152; int i = r / 9, j = r - i * 9;
        g_w2t[i * 1152 + j * 128 + o] = w2[t];
    }
    if (t < 1024) {
        const float* e = emb + t * 128;
        float s = 0.f;
        for (int d = 0; d < 128; d++) s = fmaf(e[d], e[d], s);
        g_enorm[t] = s;
        g_counts[t] = 0;
    }
}

__global__ void prep2_kernel() {
    __shared__ float mx[256];
    const int t = threadIdx.x;
    float m = 0.f;
    for (int k = t; k < 1024; k += 256) m = fmaxf(m, g_enorm[k]);
    mx[t] = m;
    __syncthreads();
    for (int off = 128; off > 0; off >>= 1) {
        if (t < off) mx[t] = fmaxf(mx[t], mx[t + off]);
        __syncthreads();
    }
    if (t == 0) { g_emax = sqrtf(mx[0]); g_fbcount = 0; }
}

// ---------------- conv1: SGEMM + fused fp16 conversion + per-pixel norms ----------------
__global__ __launch_bounds__(256) void conv1_kernel(const float* __restrict__ in,
                                                    const float* __restrict__ bias) {
    __shared__ float as[16 * 128];
    __shared__ float bs[16 * 128];
    __shared__ float pn[128][17];
    const int tid = threadIdx.x;
    const int b   = blockIdx.y;
    const int hwb = blockIdx.x * 128;
    const int m0  = (tid >> 4) * 8;
    const int n0  = (tid & 15) * 8;
    const int lr  = tid >> 4;
    const int lc  = (tid & 15) * 8;
    const float* B = in + b * (128 * HW);

    float acc[8][8];
#pragma unroll
    for (int i = 0; i < 8; i++)
#pragma unroll
        for (int j = 0; j < 8; j++) acc[i][j] = 0.f;

    for (int ks = 0; ks < 8; ks++) {
        const int c0 = ks * 16 + lr;
        __syncthreads();
        *(float4*)&as[lr * 128 + lc]     = *(const float4*)&g_w1t[c0 * 128 + lc];
        *(float4*)&as[lr * 128 + lc + 4] = *(const float4*)&g_w1t[c0 * 128 + lc + 4];
        *(float4*)&bs[lr * 128 + lc]     = *(const float4*)&B[c0 * HW + hwb + lc];
        *(float4*)&bs[lr * 128 + lc + 4] = *(const float4*)&B[c0 * HW + hwb + lc + 4];
        __syncthreads();
#pragma unroll
        for (int kk = 0; kk < 16; kk++) {
            float4 a0 = *(float4*)&as[kk * 128 + m0];
            float4 a1 = *(float4*)&as[kk * 128 + m0 + 4];
            float4 b0 = *(float4*)&bs[kk * 128 + n0];
            float4 b1 = *(float4*)&bs[kk * 128 + n0 + 4];
            float a[8] = {a0.x, a0.y, a0.z, a0.w, a1.x, a1.y, a1.z, a1.w};
            float bb[8] = {b0.x, b0.y, b0.z, b0.w, b1.x, b1.y, b1.z, b1.w};
#pragma unroll
            for (int i = 0; i < 8; i++)
#pragma unroll
                for (int j = 0; j < 8; j++) acc[i][j] = fmaf(a[i], bb[j], acc[i][j]);
        }
    }
#pragma unroll
    for (int i = 0; i < 8; i++) {
        const float bv = bias[m0 + i];
#pragma unroll
        for (int j = 0; j < 8; j++) acc[i][j] += bv;
    }
#pragma unroll
    for (int i = 0; i < 8; i++) {
        float4 v0, v1;
        v0.x = acc[i][0]; v0.y = acc[i][1]; v0.z = acc[i][2]; v0.w = acc[i][3];
        v1.x = acc[i][4]; v1.y = acc[i][5]; v1.z = acc[i][6]; v1.w = acc[i][7];
        float* dst = &g_xT[(size_t)(m0 + i) * NPIX + b * HW + hwb + n0];
        *(float4*)dst = v0;
        *(float4*)(dst + 4) = v1;
    }
#pragma unroll
    for (int j = 0; j < 8; j++) {
        const int p = b * HW + hwb + n0 + j;
        __half h[8];
#pragma unroll
        for (int i = 0; i < 8; i++) h[i] = __float2half_rn(acc[i][j]);
        *(uint4*)&g_x16[(size_t)p * 128 + m0] = *(uint4*)h;
    }
#pragma unroll
    for (int j = 0; j < 8; j++) {
        float s = 0.f;
#pragma unroll
        for (int i = 0; i < 8; i++) s = fmaf(acc[i][j], acc[i][j], s);
        pn[n0 + j][tid >> 4] = s;
    }
    __syncthreads();
    if (tid < 128) {
        float s = 0.f;
#pragma unroll
        for (int g = 0; g < 16; g++) s += pn[tid][g];
        g_xnorm[b * HW + hwb + tid] = sqrtf(s);
    }
}

// ---------------- screen: fp16 mma.sync, 128 pixels x 512 codes per block ----------------
// smem: x tile @0 (34816 B), e buf0 @34816, e buf1 @69632, enorm @104448 (2 KB)
#define PITCH  136
#define ES0    34816
#define ES1    69632
#define EN_OFF 104448
#define SCREEN_SMEM 106496

__global__ __launch_bounds__(512, 1) void screen_kernel() {
    extern __shared__ char smc[];
    const uint32_t smb = smem_to_u32(smc);
    const int tid = threadIdx.x;
    const int lane = tid & 31, wid = tid >> 5;
    const int wm = wid >> 2, wn = wid & 3;       // 4 x 4 warp grid; warp tile 32 x 32
    const int pt = blockIdx.x >> 1;              // pixel tile
    const int ch = blockIdx.x & 1;               // code half (512 codes)
    const int pbase = pt * 128;

    // x tile (128 rows x 128 d, pitch 136 halves)
#pragma unroll
    for (int j = 0; j < 4; j++) {
        const int id = j * 512 + tid, r = id >> 4, c = id & 15;
        *(uint4*)(smc + (r * PITCH + c * 8) * 2) =
            *(const uint4*)((const char*)g_x16 + (size_t)(pbase + r) * 256 + c * 16);
    }
    // e tile (ch*4 + 0)
#pragma unroll
    for (int j = 0; j < 4; j++) {
        const int id = j * 512 + tid, r = id >> 4, c = id & 15;
        *(uint4*)(smc + ES0 + (r * PITCH + c * 8) * 2) =
            *(const uint4*)((const char*)g_e16 + (size_t)(ch * 4) * 32768 + r * 256 + c * 16);
    }
    if (tid < 128) *(float4*)(smc + EN_OFF + tid * 16) = *(const float4*)&g_enorm[ch * 512 + tid * 4];
    __syncthreads();

    const float* ensm = (const float*)(smc + EN_OFF);
    float mn1[4], mn2[4]; int mi1[4];
#pragma unroll
    for (int s = 0; s < 4; s++) { mn1[s] = 3.4e38f; mn2[s] = 3.4e38f; mi1[s] = 0; }

    const uint32_t a_row = (uint32_t)(wm * 32 + (lane & 15));
    const uint32_t a_koff = (uint32_t)((lane >> 4) << 3);
    const uint32_t b_row = (uint32_t)(wn * 32 + ((lane >> 4) << 3) + (lane & 7));
    const uint32_t b_koff = (uint32_t)(((lane >> 3) & 1) << 3);

    for (int nt = 0; nt < 4; nt++) {
        const int ebase = (nt & 1) ? ES1 : ES0;
        float acc[2][4][4];
#pragma unroll
        for (int mt = 0; mt < 2; mt++)
#pragma unroll
            for (int ntl = 0; ntl < 4; ntl++)
#pragma unroll
                for (int c = 0; c < 4; c++) acc[mt][ntl][c] = 0.f;

        if (nt < 3) {  // prefetch next e tile into the other buffer
            const char* src = (const char*)g_e16 + (size_t)(ch * 4 + nt + 1) * 32768;
            char* dst = smc + ((nt & 1) ? ES0 : ES1);
#pragma unroll
            for (int j = 0; j < 4; j++) {
                const int id = j * 512 + tid, r = id >> 4, c = id & 15;
                *(uint4*)(dst + (r * PITCH + c * 8) * 2) = *(const uint4*)(src + r * 256 + c * 16);
            }
        }
#pragma unroll
        for (int kk = 0; kk < 8; kk++) {
            uint32_t a[2][4];
#pragma unroll
            for (int mt = 0; mt < 2; mt++) {
                const uint32_t addr = smb + ((a_row + mt * 16) * PITCH + kk * 16 + a_koff) * 2;
                ldsm_x4(a[mt][0], a[mt][1], a[mt][2], a[mt][3], addr);
            }
            uint32_t b[4][2];
#pragma unroll
            for (int nb = 0; nb < 2; nb++) {
                uint32_t r0, r1, r2, r3;
                const uint32_t addr = smb + ebase + ((b_row + nb * 16) * PITCH + kk * 16 + b_koff) * 2;
                ldsm_x4(r0, r1, r2, r3, addr);
                b[nb * 2][0] = r0; b[nb * 2][1] = r1;
                b[nb * 2 + 1][0] = r2; b[nb * 2 + 1][1] = r3;
            }
#pragma unroll
            for (int mt = 0; mt < 2; mt++)
#pragma unroll
                for (int ntl = 0; ntl < 4; ntl++) mma16816(acc[mt][ntl], a[mt], b[ntl]);
        }
        // scores + running top-2 (ties land in fallback, so plain < is safe)
#pragma unroll
        for (int mt = 0; mt < 2; mt++)
#pragma unroll
            for (int c = 0; c < 4; c++) {
                const int slot = mt * 2 + (c >> 1);
#pragma unroll
                for (int ntl = 0; ntl < 4; ntl++) {
                    const int col = nt * 128 + wn * 32 + ntl * 8 + ((lane & 3) << 1) + (c & 1);
                    const float s = fmaf(-2.f, acc[mt][ntl][c], ensm[col]);
                    if (s < mn1[slot]) { mn2[slot] = mn1[slot]; mn1[slot] = s; mi1[slot] = col; }
                    else if (s < mn2[slot]) mn2[slot] = s;
                }
            }
        __syncthreads();
    }

    // in-warp merge across the 4 lanes sharing each row (lane&3 partitions cols)
#pragma unroll
    for (int s = 0; s < 4; s++) {
#pragma unroll
        for (int m = 1; m <= 2; m <<= 1) {
            const float o1 = __shfl_xor_sync(0xffffffffu, mn1[s], m);
            const float o2 = __shfl_xor_sync(0xffffffffu, mn2[s], m);
            const int   oi = __shfl_xor_sync(0xffffffffu, mi1[s], m);
            if (o1 < mn1[s]) { mn2[s] = fminf(mn1[s], o2); mn1[s] = o1; mi1[s] = oi; }
            else mn2[s] = fminf(mn2[s], o1);
        }
    }
    // cross-warp merge via smem (x region dead: 6 KB < 34 KB)
    float* f1 = (float*)smc;
    int*   j1 = (int*)(smc + 2048);
    float* f2 = (float*)(smc + 4096);
    if ((lane & 3) == 0) {
#pragma unroll
        for (int s = 0; s < 4; s++) {
            const int row = wm * 32 + (s >> 1) * 16 + (s & 1) * 8 + (lane >> 2);
            f1[row * 4 + wn] = mn1[s];
            j1[row * 4 + wn] = mi1[s];
            f2[row * 4 + wn] = mn2[s];
        }
    }
    __syncthreads();
    if (tid < 128) {
        float m1 = f1[tid * 4], m2 = f2[tid * 4];
        int i1 = j1[tid * 4];
#pragma unroll
        for (int w = 1; w < 4; w++) {
            const float o1 = f1[tid * 4 + w], o2 = f2[tid * 4 + w];
            const int oi = j1[tid * 4 + w];
            if (o1 < m1) { m2 = fminf(m1, o2); m1 = o1; i1 = oi; }
            else m2 = fminf(m2, o1);
        }
        const int p = pbase + tid;
        g_sm1[ch * NPIX + p] = m1;
        g_si1[ch * NPIX + p] = ch * 512 + i1;
        g_sm2[ch * NPIX + p] = m2;
    }
}

// ---------------- merge halves + margin test ----------------
__global__ __launch_bounds__(256) void merge_kernel() {
    const int p = blockIdx.x * blockDim.x + threadIdx.x;
    const float a1 = g_sm1[p], b1 = g_sm1[NPIX + p];
    const float a2 = g_sm2[p], b2 = g_sm2[NPIX + p];
    const int ia = g_si1[p], ib = g_si1[NPIX + p];
    float m1, m2; int i1;
    if (a1 < b1 || (a1 == b1 && ia < ib)) { m1 = a1; i1 = ia; m2 = fminf(a2, b1); }
    else { m1 = b1; i1 = ib; m2 = fminf(b2, a1); }
    g_idx[p] = i1;
    const float thresh = fmaf(4.5e-3f * g_emax, g_xnorm[p], 1e-5f);
    if (m2 - m1 <= thresh) {
        const int pos = atomicAdd(&g_fbcount, 1);
        g_fblist[pos] = p;
    }
}

// ---------------- full fallback: exact fp32 SGEMM-argmin over flagged pixels ----------------
__global__ __launch_bounds__(256) void fb_kernel() {
    extern __shared__ float sm[];
    float* xs = sm;
    float* bs = sm + 16384;
    int*   pl = (int*)(sm + 18432);
    unsigned long long* red = (unsigned long long*)sm;

    const int tid = threadIdx.x;
    const int cnt = g_fbcount;
    const int ntiles = (cnt + 127) >> 7;

    for (int t = blockIdx.x; t < ntiles; t += gridDim.x) {
        __syncthreads();
        if (tid < 128) {
            const int li = t * 128 + tid;
            pl[tid] = (li < cnt) ? g_fblist[li] : g_fblist[0];
        }
        __syncthreads();
        {
            const int i = tid & 127;
            const int p = pl[i];
#pragma unroll 4
            for (int j = 0; j < 64; j++) {
                const int d = (tid >> 7) + j * 2;
                xs[d * 128 + i] = g_xT[(size_t)d * NPIX + p];
            }
        }
        __syncthreads();

        const int m0 = (tid >> 4) * 8;
        const int n0 = (tid & 15) * 8;
        const int lr = tid >> 4;
        const int lc = (tid & 15) * 8;

        float minv[8]; int mini[8];
#pragma unroll
        for (int i = 0; i < 8; i++) { minv[i] = 3.4e38f; mini[i] = 0; }

        for (int nt = 0; nt < 8; nt++) {
            const int kb = nt * 128;
            float acc[8][8];
#pragma unroll
            for (int i = 0; i < 8; i++)
#pragma unroll
                for (int j = 0; j < 8; j++) acc[i][j] = 0.f;

            for (int ks = 0; ks < 8; ks++) {
                const int r = ks * 16 + lr;
                __syncthreads();
                *(float4*)&bs[lr * 128 + lc]     = *(const float4*)&g_eT[r * 1024 + kb + lc];
                *(float4*)&bs[lr * 128 + lc + 4] = *(const float4*)&g_eT[r * 1024 + kb + lc + 4];
                __syncthreads();
#pragma unroll
                for (int kk = 0; kk < 16; kk++) {
                    const int dd = ks * 16 + kk;
                    float4 a0 = *(float4*)&xs[dd * 128 + m0];
                    float4 a1 = *(float4*)&xs[dd * 128 + m0 + 4];
                    float4 b0 = *(float4*)&bs[kk * 128 + n0];
                    float4 b1 = *(float4*)&bs[kk * 128 + n0 + 4];
                    float a[8] = {a0.x, a0.y, a0.z, a0.w, a1.x, a1.y, a1.z, a1.w};
                    float bb[8] = {b0.x, b0.y, b0.z, b0.w, b1.x, b1.y, b1.z, b1.w};
#pragma unroll
                    for (int i = 0; i < 8; i++)
#pragma unroll
                        for (int j = 0; j < 8; j++) acc[i][j] = fmaf(a[i], bb[j], acc[i][j]);
                }
            }
#pragma unroll
            for (int j = 0; j < 8; j++) {
                const float en = g_enorm[kb + n0 + j];
#pragma unroll
                for (int i = 0; i < 8; i++) {
                    float s = fmaf(-2.f, acc[i][j], en);
                    if (s < minv[i]) { minv[i] = s; mini[i] = kb + n0 + j; }
                }
            }
        }
        __syncthreads();
#pragma unroll
        for (int i = 0; i < 8; i++) {
            unsigned int fb = __float_as_uint(minv[i]);
            fb = (fb & 0x80000000u) ? ~fb : (fb | 0x80000000u);
            red[(m0 + i) * 16 + (tid & 15)] = ((unsigned long long)fb << 32) | (unsigned int)mini[i];
        }
        __syncthreads();
        if (tid < 128) {
            unsigned long long m = red[tid * 16];
#pragma unroll
            for (int q = 1; q < 16; q++) {
                unsigned long long v = red[tid * 16 + q];
                if (v < m) m = v;
            }
            g_idx[pl[tid]] = (int)(m & 0xffffffffu);
        }
    }
}

// ---------------- U precompute GEMM ----------------
__global__ __launch_bounds__(256) void ugemm_kernel() {
    __shared__ float as[16 * 128];
    __shared__ float bs[16 * 128];
    const int tid = threadIdx.x;
    const int mb = blockIdx.y * 128;
    const int nb = blockIdx.x * 128;
    const int m0 = (tid >> 4) * 8;
    const int n0 = (tid & 15) * 8;
    const int lr = tid >> 4;
    const int lc = (tid & 15) * 8;

    float acc[8][8];
#pragma unroll
    for (int i = 0; i < 8; i++)
#pragma unroll
        for (int j = 0; j < 8; j++) acc[i][j] = 0.f;

    for (int ks = 0; ks < 8; ks++) {
        const int r = ks * 16 + lr;
        __syncthreads();
        *(float4*)&as[lr * 128 + lc]     = *(const float4*)&g_eT[r * 1024 + mb + lc];
        *(float4*)&as[lr * 128 + lc + 4] = *(const float4*)&g_eT[r * 1024 + mb + lc + 4];
        *(float4*)&bs[lr * 128 + lc]     = *(const float4*)&g_w2t[r * 1152 + nb + lc];
        *(float4*)&bs[lr * 128 + lc + 4] = *(const float4*)&g_w2t[r * 1152 + nb + lc + 4];
        __syncthreads();
#pragma unroll
        for (int kk = 0; kk < 16; kk++) {
            float4 a0 = *(float4*)&as[kk * 128 + m0];
            float4 a1 = *(float4*)&as[kk * 128 + m0 + 4];
            float4 b0 = *(float4*)&bs[kk * 128 + n0];
            float4 b1 = *(float4*)&bs[kk * 128 + n0 + 4];
            float a[8] = {a0.x, a0.y, a0.z, a0.w, a1.x, a1.y, a1.z, a1.w};
            float bb[8] = {b0.x, b0.y, b0.z, b0.w, b1.x, b1.y, b1.z, b1.w};
#pragma unroll
            for (int i = 0; i < 8; i++)
#pragma unroll
                for (int j = 0; j < 8; j++) acc[i][j] = fmaf(a[i], bb[j], acc[i][j]);
        }
    }
#pragma unroll
    for (int i = 0; i < 8; i++) {
        float4 v0, v1;
        v0.x = acc[i][0]; v0.y = acc[i][1]; v0.z = acc[i][2]; v0.w = acc[i][3];
        v1.x = acc[i][4]; v1.y = acc[i][5]; v1.z = acc[i][6]; v1.w = acc[i][7];
        float* dst = &g_U[(size_t)(mb + m0 + i) * 1152 + nb + n0];
        *(float4*)dst = v0;
        *(float4*)(dst + 4) = v1;
    }
}

// ---------------- gather: quant write, loss partials, counts, idx out ----------------
__global__ __launch_bounds__(256) void gather_kernel(const float* __restrict__ emb,
                                                     float* __restrict__ out) {
    __shared__ float qs[64 * 132];
    __shared__ int sc[64];
    __shared__ float lred[8];
    const int tid = threadIdx.x;
    const int pbase = blockIdx.x * 64;
    const int w = tid >> 5, lane = tid & 31;

#pragma unroll
    for (int it = 0; it < 8; it++) {
        const int pl = w * 8 + it;
        const int c = g_idx[pbase + pl];
        float4 v = *(const float4*)&emb[c * 128 + lane * 4];
        *(float4*)&qs[pl * 132 + lane * 4] = v;
        if (lane == 0) { sc[pl] = c; atomicAdd(&g_counts[c], 1); }
    }
    __syncthreads();

    const int pl = tid & 63, dg = tid >> 6;
    const int p = pbase + pl;
    const int b = p >> 12, hw = p & 4095;
    float lsum = 0.f;
#pragma unroll
    for (int dd = 0; dd < 32; dd++) {
        const int d = dg * 32 + dd;
        const float q = qs[pl * 132 + d];
        const float x = g_xT[(size_t)d * NPIX + p];
        const float df = q - x;
        lsum = fmaf(df, df, lsum);
        out[Q_OFF + b * (128 * HW) + d * HW + hw] = q;
    }
#pragma unroll
    for (int off = 16; off > 0; off >>= 1) lsum += __shfl_down_sync(0xffffffffu, lsum, off);
    if (lane == 0) lred[w] = lsum;
    __syncthreads();
    if (tid == 0) {
        float s = 0.f;
        for (int i = 0; i < 8; i++) s += lred[i];
        g_lpart[blockIdx.x] = s;
    }
    if (tid < 64) out[IDX_OFF + pbase + tid] = (float)sc[tid];
}

// ---------------- conv2 via U table ----------------
__global__ __launch_bounds__(256) void conv2_kernel(const float* __restrict__ bias,
                                                    float* __restrict__ out) {
    __shared__ int nid[3][66];
    const int tid = threadIdx.x;
    const int y = blockIdx.x, b = blockIdx.y;
    if (tid < 198) {
        const int r = tid / 66, xi = tid % 66 - 1;
        const int yy = y + r - 1;
        int v = -1;
        if (yy >= 0 && yy < 64 && xi >= 0 && xi < 64) v = g_idx[b * HW + yy * 64 + xi];
        nid[r][tid % 66] = v;
    }
    __syncthreads();

    const int x = tid & 63, og = tid >> 6;
    const int ob = og * 32;
    float acc[32];
#pragma unroll
    for (int u = 0; u < 32; u++) acc[u] = bias[ob + u];

#pragma unroll
    for (int ky = 0; ky < 3; ky++)
#pragma unroll
        for (int kx = 0; kx < 3; kx++) {
            const int c = nid[ky][x + kx];
            if (c >= 0) {
                const float4* Up = (const float4*)&g_U[(size_t)c * 1152 + (ky * 3 + kx) * 128 + ob];
#pragma unroll
                for (int u4 = 0; u4 < 8; u4++) {
                    float4 v = Up[u4];
                    acc[u4 * 4 + 0] += v.x; acc[u4 * 4 + 1] += v.y;
                    acc[u4 * 4 + 2] += v.z; acc[u4 * 4 + 3] += v.w;
                }
            }
        }
    const int base = NV_OFF + b * (128 * HW) + y * 64 + x;
#pragma unroll
    for (int u = 0; u < 32; u++) out[base + (ob + u) * HW] = acc[u];
}

// ---------------- finalize ----------------
__global__ void finalize_kernel(float* __restrict__ out) {
    __shared__ double ds[256];
    __shared__ float hs[256];
    const int t = threadIdx.x;
    double s = 0.0;
    float h = 0.f;
    for (int k = t; k < 1024; k += 256) {
        s += (double)g_lpart[k];
        const float avg = (float)g_counts[k] * (1.0f / 65536.0f);
        h += avg * logf(avg + 1e-10f);
    }
    ds[t] = s; hs[t] = h;
    __syncthreads();
    for (int off = 128; off > 0; off >>= 1) {
        if (t < off) { ds[t] += ds[t + off]; hs[t] += hs[t + off]; }
        __syncthreads();
    }
    if (t == 0) {
        out[0] = (float)(1.25 * ds[0] / 8388608.0);
        out[PERP_OFF] = expf(-hs[0]);
    }
}

// ---------------- launch (screen is 4th: profiled slot) ----------------
extern "C" void kernel_launch(void* const* d_in, const int* in_sizes, int n_in,
                              void* d_out, int out_size) {
    const float* in  = (const float*)d_in[0];
    const float* w1  = (const float*)d_in[1];
    const float* b1  = (const float*)d_in[2];
    const float* emb = (const float*)d_in[3];
    const float* w2  = (const float*)d_in[4];
    const float* b2  = (const float*)d_in[5];
    float* out = (float*)d_out;

    cudaFuncSetAttribute(screen_kernel, cudaFuncAttributeMaxDynamicSharedMemorySize, SCREEN_SMEM);
    cudaFuncSetAttribute(fb_kernel, cudaFuncAttributeMaxDynamicSharedMemorySize, 74240);

    prep_kernel<<<576, 256>>>(emb, w1, w2);
    prep2_kernel<<<1, 256>>>();
    conv1_kernel<<<dim3(32, 16), 256>>>(in, b1);
    screen_kernel<<<1024, 512, SCREEN_SMEM>>>();
    merge_kernel<<<256, 256>>>();
    fb_kernel<<<64, 256, 74240>>>();
    ugemm_kernel<<<dim3(9, 8), 256>>>();
    gather_kernel<<<1024, 256>>>(emb, out);
    conv2_kernel<<<dim3(64, 16), 256>>>(b2, out);
    finalize_kernel<<<1, 256>>>(out);
}

// round 7
// speedup vs baseline: 1.1479x; 1.0137x over previous
#include <cuda_runtime.h>
#include <cuda_fp16.h>
#include <math.h>
#include <stdint.h>

#define NPIX   65536
#define HW     4096

#define Q_OFF    1
#define NV_OFF   8388609
#define PERP_OFF 16777217
#define IDX_OFF  16777218

// ---------------- scratch (static device arrays; no allocations) ----------------
__device__ float g_xT[128 * NPIX];       // conv1 output, transposed [d][p] (32 MB)
__device__ float g_eT[128 * 1024];       // emb transposed [d][k]
__device__ float g_enorm[1024];          // ||e_k||^2
__device__ float g_w1t[128 * 128];
__device__ float g_w2t[128 * 1152];
__device__ float g_U[1024 * 1152];
__device__ int   g_idx[NPIX];
__device__ int   g_counts[1024];
__device__ float g_lpart[1024];
__device__ float g_xnorm[NPIX];
__device__ float g_emax;
__device__ int   g_fbcount;
__device__ int   g_fblist[NPIX];
__device__ float g_sm1[2 * NPIX];        // per-half top-1 score
__device__ int   g_si1[2 * NPIX];        // per-half top-1 col (global)
__device__ float g_sm2[2 * NPIX];        // per-half top-2 score
__device__ __align__(16) __half g_x16[NPIX * 128];   // x fp16, row-major [p][d]
__device__ __align__(16) __half g_e16[1024 * 128];   // e fp16, row-major [k][d]

// ---------------- warp MMA helpers (baseline PTX, sm_80+) ----------------
__device__ __forceinline__ uint32_t smem_to_u32(const void* p) {
    uint32_t a;
    asm("{ .reg .u64 t; cvta.to.shared.u64 t, %1; cvt.u32.u64 %0, t; }" : "=r"(a) : "l"(p));
    return a;
}
__device__ __forceinline__ void ldsm_x4(uint32_t& r0, uint32_t& r1, uint32_t& r2, uint32_t& r3, uint32_t addr) {
    asm volatile("ldmatrix.sync.aligned.m8n8.x4.shared.b16 {%0,%1,%2,%3}, [%4];"
                 : "=r"(r0), "=r"(r1), "=r"(r2), "=r"(r3) : "r"(addr));
}
__device__ __forceinline__ void mma16816(float* c, const uint32_t* a, const uint32_t* b) {
    asm volatile("mma.sync.aligned.m16n8k16.row.col.f32.f16.f16.f32 "
                 "{%0,%1,%2,%3}, {%4,%5,%6,%7}, {%8,%9}, {%0,%1,%2,%3};"
                 : "+f"(c[0]), "+f"(c[1]), "+f"(c[2]), "+f"(c[3])
                 : "r"(a[0]), "r"(a[1]), "r"(a[2]), "r"(a[3]), "r"(b[0]), "r"(b[1]));
}
__device__ __forceinline__ void cp_async16(uint32_t smem_addr, const void* gptr) {
    asm volatile("cp.async.cg.shared.global [%0], [%1], 16;" :: "r"(smem_addr), "l"(gptr));
}
#define CP_COMMIT() asm volatile("cp.async.commit_group;" ::: "memory")
#define CP_WAIT0()  asm volatile("cp.async.wait_group 0;" ::: "memory")

// ---------------- prep ----------------
__global__ void prep_kernel(const float* __restrict__ emb,
                            const float* __restrict__ w1,
                            const float* __restrict__ w2) {
    int t = blockIdx.x * blockDim.x + threadIdx.x;
    if (t < 131072) {
        int k = t >> 7, d = t & 127;
        float v = emb[t];
        g_eT[d * 1024 + k] = v;
        g_e16[t] = __float2half_rn(v);
    }
    if (t < 16384)  { int d = t >> 7, c = t & 127; g_w1t[c * 128 + d] = w1[t]; }
    if (t < 147456) {
        int o = t / 1152; int r = t - o * 1152; int i = r / 9, j = r - i * 9;
        g_w2t[i * 1152 + j * 128 + o] = w2[t];
    }
    if (t < 1024) {
        const float* e = emb + t * 128;
        float s = 0.f;
        for (int d = 0; d < 128; d++) s = fmaf(e[d], e[d], s);
        g_enorm[t] = s;
        g_counts[t] = 0;
    }
}

__global__ void prep2_kernel() {
    __shared__ float mx[256];
    const int t = threadIdx.x;
    float m = 0.f;
    for (int k = t; k < 1024; k += 256) m = fmaxf(m, g_enorm[k]);
    mx[t] = m;
    __syncthreads();
    for (int off = 128; off > 0; off >>= 1) {
        if (t < off) mx[t] = fmaxf(mx[t], mx[t + off]);
        __syncthreads();
    }
    if (t == 0) { g_emax = sqrtf(mx[0]); g_fbcount = 0; }
}

// ---------------- conv1: SGEMM + fused fp16 conversion + per-pixel norms ----------------
__global__ __launch_bounds__(256) void conv1_kernel(const float* __restrict__ in,
                                                    const float* __restrict__ bias) {
    __shared__ float as[16 * 128];
    __shared__ float bs[16 * 128];
    __shared__ float pn[128][17];
    const int tid = threadIdx.x;
    const int b   = blockIdx.y;
    const int hwb = blockIdx.x * 128;
    const int m0  = (tid >> 4) * 8;
    const int n0  = (tid & 15) * 8;
    const int lr  = tid >> 4;
    const int lc  = (tid & 15) * 8;
    const float* B = in + b * (128 * HW);

    float acc[8][8];
#pragma unroll
    for (int i = 0; i < 8; i++)
#pragma unroll
        for (int j = 0; j < 8; j++) acc[i][j] = 0.f;

    for (int ks = 0; ks < 8; ks++) {
        const int c0 = ks * 16 + lr;
        __syncthreads();
        *(float4*)&as[lr * 128 + lc]     = *(const float4*)&g_w1t[c0 * 128 + lc];
        *(float4*)&as[lr * 128 + lc + 4] = *(const float4*)&g_w1t[c0 * 128 + lc + 4];
        *(float4*)&bs[lr * 128 + lc]     = *(const float4*)&B[c0 * HW + hwb + lc];
        *(float4*)&bs[lr * 128 + lc + 4] = *(const float4*)&B[c0 * HW + hwb + lc + 4];
        __syncthreads();
#pragma unroll
        for (int kk = 0; kk < 16; kk++) {
            float4 a0 = *(float4*)&as[kk * 128 + m0];
            float4 a1 = *(float4*)&as[kk * 128 + m0 + 4];
            float4 b0 = *(float4*)&bs[kk * 128 + n0];
            float4 b1 = *(float4*)&bs[kk * 128 + n0 + 4];
            float a[8] = {a0.x, a0.y, a0.z, a0.w, a1.x, a1.y, a1.z, a1.w};
            float bb[8] = {b0.x, b0.y, b0.z, b0.w, b1.x, b1.y, b1.z, b1.w};
#pragma unroll
            for (int i = 0; i < 8; i++)
#pragma unroll
                for (int j = 0; j < 8; j++) acc[i][j] = fmaf(a[i], bb[j], acc[i][j]);
        }
    }
#pragma unroll
    for (int i = 0; i < 8; i++) {
        const float bv = bias[m0 + i];
#pragma unroll
        for (int j = 0; j < 8; j++) acc[i][j] += bv;
    }
#pragma unroll
    for (int i = 0; i < 8; i++) {
        float4 v0, v1;
        v0.x = acc[i][0]; v0.y = acc[i][1]; v0.z = acc[i][2]; v0.w = acc[i][3];
        v1.x = acc[i][4]; v1.y = acc[i][5]; v1.z = acc[i][6]; v1.w = acc[i][7];
        float* dst = &g_xT[(size_t)(m0 + i) * NPIX + b * HW + hwb + n0];
        *(float4*)dst = v0;
        *(float4*)(dst + 4) = v1;
    }
#pragma unroll
    for (int j = 0; j < 8; j++) {
        const int p = b * HW + hwb + n0 + j;
        __half h[8];
#pragma unroll
        for (int i = 0; i < 8; i++) h[i] = __float2half_rn(acc[i][j]);
        *(uint4*)&g_x16[(size_t)p * 128 + m0] = *(uint4*)h;
    }
#pragma unroll
    for (int j = 0; j < 8; j++) {
        float s = 0.f;
#pragma unroll
        for (int i = 0; i < 8; i++) s = fmaf(acc[i][j], acc[i][j], s);
        pn[n0 + j][tid >> 4] = s;
    }
    __syncthreads();
    if (tid < 128) {
        float s = 0.f;
#pragma unroll
        for (int g = 0; g < 16; g++) s += pn[tid][g];
        g_xnorm[b * HW + hwb + tid] = sqrtf(s);
    }
}

// ---------------- screen: fp16 mma.sync, pipelined ldsm + cp.async ----------------
// smem: x tile @0 (34816 B), e buf0 @34816, e buf1 @69632, enorm @104448 (2 KB)
#define PITCH  136
#define ES0    34816
#define ES1    69632
#define EN_OFF 104448
#define SCREEN_SMEM 106496

__global__ __launch_bounds__(512, 1) void screen_kernel() {
    extern __shared__ char smc[];
    const uint32_t smb = smem_to_u32(smc);
    const int tid = threadIdx.x;
    const int lane = tid & 31, wid = tid >> 5;
    const int wm = wid >> 2, wn = wid & 3;       // 4 x 4 warp grid; warp tile 32 x 32
    const int pt = blockIdx.x >> 1;              // pixel tile
    const int ch = blockIdx.x & 1;               // code half (512 codes)
    const int pbase = pt * 128;

    // x tile (128 rows x 128 d, pitch 136 halves) via cp.async
#pragma unroll
    for (int j = 0; j < 4; j++) {
        const int id = j * 512 + tid, r = id >> 4, c = id & 15;
        cp_async16(smb + (uint32_t)(r * PITCH + c * 8) * 2,
                   (const char*)g_x16 + (size_t)(pbase + r) * 256 + c * 16);
    }
    // e tile (ch*4 + 0)
#pragma unroll
    for (int j = 0; j < 4; j++) {
        const int id = j * 512 + tid, r = id >> 4, c = id & 15;
        cp_async16(smb + ES0 + (uint32_t)(r * PITCH + c * 8) * 2,
                   (const char*)g_e16 + (size_t)(ch * 4) * 32768 + r * 256 + c * 16);
    }
    if (tid < 128) *(float4*)(smc + EN_OFF + tid * 16) = *(const float4*)&g_enorm[ch * 512 + tid * 4];
    CP_COMMIT();
    CP_WAIT0();
    __syncthreads();

    const float* ensm = (const float*)(smc + EN_OFF);
    float mn1[4], mn2[4]; int mi1[4];
#pragma unroll
    for (int s = 0; s < 4; s++) { mn1[s] = 3.4e38f; mn2[s] = 3.4e38f; mi1[s] = 0; }

    const uint32_t a_row = (uint32_t)(wm * 32 + (lane & 15));
    const uint32_t a_koff = (uint32_t)((lane >> 4) << 3);
    const uint32_t b_row = (uint32_t)(wn * 32 + ((lane >> 4) << 3) + (lane & 7));
    const uint32_t b_koff = (uint32_t)(((lane >> 3) & 1) << 3);

    for (int nt = 0; nt < 4; nt++) {
        const int ebase = (nt & 1) ? ES1 : ES0;
        float acc[2][4][4];
#pragma unroll
        for (int mt = 0; mt < 2; mt++)
#pragma unroll
            for (int ntl = 0; ntl < 4; ntl++)
#pragma unroll
                for (int c = 0; c < 4; c++) acc[mt][ntl][c] = 0.f;

        if (nt < 3) {  // async prefetch next e tile into the other buffer
            const char* src = (const char*)g_e16 + (size_t)(ch * 4 + nt + 1) * 32768;
            const uint32_t dst = smb + ((nt & 1) ? ES0 : ES1);
#pragma unroll
            for (int j = 0; j < 4; j++) {
                const int id = j * 512 + tid, r = id >> 4, c = id & 15;
                cp_async16(dst + (uint32_t)(r * PITCH + c * 8) * 2, src + r * 256 + c * 16);
            }
            CP_COMMIT();
        }

        // software-pipelined ldsm: frags for kk+1 loaded during kk's mma
        uint32_t a[2][2][4], b[2][4][2];
        {
#pragma unroll
            for (int mt = 0; mt < 2; mt++) {
                const uint32_t addr = smb + ((a_row + mt * 16) * PITCH + a_koff) * 2;
                ldsm_x4(a[0][mt][0], a[0][mt][1], a[0][mt][2], a[0][mt][3], addr);
            }
#pragma unroll
            for (int nb = 0; nb < 2; nb++) {
                uint32_t r0, r1, r2, r3;
                const uint32_t addr = smb + ebase + ((b_row + nb * 16) * PITCH + b_koff) * 2;
                ldsm_x4(r0, r1, r2, r3, addr);
                b[0][nb * 2][0] = r0; b[0][nb * 2][1] = r1;
                b[0][nb * 2 + 1][0] = r2; b[0][nb * 2 + 1][1] = r3;
            }
        }
#pragma unroll
        for (int kk = 0; kk < 8; kk++) {
            const int cur = kk & 1, nxt = cur ^ 1;
            if (kk < 7) {
                const int k2 = (kk + 1) * 16;
#pragma unroll
                for (int mt = 0; mt < 2; mt++) {
                    const uint32_t addr = smb + ((a_row + mt * 16) * PITCH + k2 + a_koff) * 2;
                    ldsm_x4(a[nxt][mt][0], a[nxt][mt][1], a[nxt][mt][2], a[nxt][mt][3], addr);
                }
#pragma unroll
                for (int nb = 0; nb < 2; nb++) {
                    uint32_t r0, r1, r2, r3;
                    const uint32_t addr = smb + ebase + ((b_row + nb * 16) * PITCH + k2 + b_koff) * 2;
                    ldsm_x4(r0, r1, r2, r3, addr);
                    b[nxt][nb * 2][0] = r0; b[nxt][nb * 2][1] = r1;
                    b[nxt][nb * 2 + 1][0] = r2; b[nxt][nb * 2 + 1][1] = r3;
                }
            }
#pragma unroll
            for (int mt = 0; mt < 2; mt++)
#pragma unroll
                for (int ntl = 0; ntl < 4; ntl++) mma16816(acc[mt][ntl], a[cur][mt], b[cur][ntl]);
        }
        // scores + running top-2 (ties land in fallback, so plain < is safe)
#pragma unroll
        for (int mt = 0; mt < 2; mt++)
#pragma unroll
            for (int c = 0; c < 4; c++) {
                const int slot = mt * 2 + (c >> 1);
#pragma unroll
                for (int ntl = 0; ntl < 4; ntl++) {
                    const int col = nt * 128 + wn * 32 + ntl * 8 + ((lane & 3) << 1) + (c & 1);
                    const float s = fmaf(-2.f, acc[mt][ntl][c], ensm[col]);
                    if (s < mn1[slot]) { mn2[slot] = mn1[slot]; mn1[slot] = s; mi1[slot] = col; }
                    else if (s < mn2[slot]) mn2[slot] = s;
                }
            }
        if (nt < 3) CP_WAIT0();
        __syncthreads();
    }

    // in-warp merge across the 4 lanes sharing each row (lane&3 partitions cols)
#pragma unroll
    for (int s = 0; s < 4; s++) {
#pragma unroll
        for (int m = 1; m <= 2; m <<= 1) {
            const float o1 = __shfl_xor_sync(0xffffffffu, mn1[s], m);
            const float o2 = __shfl_xor_sync(0xffffffffu, mn2[s], m);
            const int   oi = __shfl_xor_sync(0xffffffffu, mi1[s], m);
            if (o1 < mn1[s]) { mn2[s] = fminf(mn1[s], o2); mn1[s] = o1; mi1[s] = oi; }
            else mn2[s] = fminf(mn2[s], o1);
        }
    }
    // cross-warp merge via smem (x region dead: 6 KB < 34 KB)
    float* f1 = (float*)smc;
    int*   j1 = (int*)(smc + 2048);
    float* f2 = (float*)(smc + 4096);
    if ((lane & 3) == 0) {
#pragma unroll
        for (int s = 0; s < 4; s++) {
            const int row = wm * 32 + (s >> 1) * 16 + (s & 1) * 8 + (lane >> 2);
            f1[row * 4 + wn] = mn1[s];
            j1[row * 4 + wn] = mi1[s];
            f2[row * 4 + wn] = mn2[s];
        }
    }
    __syncthreads();
    if (tid < 128) {
        float m1 = f1[tid * 4], m2 = f2[tid * 4];
        int i1 = j1[tid * 4];
#pragma unroll
        for (int w = 1; w < 4; w++) {
            const float o1 = f1[tid * 4 + w], o2 = f2[tid * 4 + w];
            const int oi = j1[tid * 4 + w];
            if (o1 < m1) { m2 = fminf(m1, o2); m1 = o1; i1 = oi; }
            else m2 = fminf(m2, o1);
        }
        const int p = pbase + tid;
        g_sm1[ch * NPIX + p] = m1;
        g_si1[ch * NPIX + p] = ch * 512 + i1;
        g_sm2[ch * NPIX + p] = m2;
    }
}

// ---------------- merge halves + margin test ----------------
__global__ __launch_bounds__(256) void merge_kernel() {
    const int p = blockIdx.x * blockDim.x + threadIdx.x;
    const float a1 = g_sm1[p], b1 = g_sm1[NPIX + p];
    const float a2 = g_sm2[p], b2 = g_sm2[NPIX + p];
    const int ia = g_si1[p], ib = g_si1[NPIX + p];
    float m1, m2; int i1;
    if (a1 < b1 || (a1 == b1 && ia < ib)) { m1 = a1; i1 = ia; m2 = fminf(a2, b1); }
    else { m1 = b1; i1 = ib; m2 = fminf(b2, a1); }
    g_idx[p] = i1;
    const float thresh = fmaf(4.5e-3f * g_emax, g_xnorm[p], 1e-5f);
    if (m2 - m1 <= thresh) {
        const int pos = atomicAdd(&g_fbcount, 1);
        g_fblist[pos] = p;
    }
}

// ---------------- full fallback: exact fp32 SGEMM-argmin over flagged pixels ----------------
__global__ __launch_bounds__(256) void fb_kernel() {
    extern __shared__ float sm[];
    float* xs = sm;
    float* bs = sm + 16384;
    int*   pl = (int*)(sm + 18432);
    unsigned long long* red = (unsigned long long*)sm;

    const int tid = threadIdx.x;
    const int cnt = g_fbcount;
    const int ntiles = (cnt + 127) >> 7;

    for (int t = blockIdx.x; t < ntiles; t += gridDim.x) {
        __syncthreads();
        if (tid < 128) {
            const int li = t * 128 + tid;
            pl[tid] = (li < cnt) ? g_fblist[li] : g_fblist[0];
        }
        __syncthreads();
        {
            const int i = tid & 127;
            const int p = pl[i];
#pragma unroll 4
            for (int j = 0; j < 64; j++) {
                const int d = (tid >> 7) + j * 2;
                xs[d * 128 + i] = g_xT[(size_t)d * NPIX + p];
            }
        }
        __syncthreads();

        const int m0 = (tid >> 4) * 8;
        const int n0 = (tid & 15) * 8;
        const int lr = tid >> 4;
        const int lc = (tid & 15) * 8;

        float minv[8]; int mini[8];
#pragma unroll
        for (int i = 0; i < 8; i++) { minv[i] = 3.4e38f; mini[i] = 0; }

        for (int nt = 0; nt < 8; nt++) {
            const int kb = nt * 128;
            float acc[8][8];
#pragma unroll
            for (int i = 0; i < 8; i++)
#pragma unroll
                for (int j = 0; j < 8; j++) acc[i][j] = 0.f;

            for (int ks = 0; ks < 8; ks++) {
                const int r = ks * 16 + lr;
                __syncthreads();
                *(float4*)&bs[lr * 128 + lc]     = *(const float4*)&g_eT[r * 1024 + kb + lc];
                *(float4*)&bs[lr * 128 + lc + 4] = *(const float4*)&g_eT[r * 1024 + kb + lc + 4];
                __syncthreads();
#pragma unroll
                for (int kk = 0; kk < 16; kk++) {
                    const int dd = ks * 16 + kk;
                    float4 a0 = *(float4*)&xs[dd * 128 + m0];
                    float4 a1 = *(float4*)&xs[dd * 128 + m0 + 4];
                    float4 b0 = *(float4*)&bs[kk * 128 + n0];
                    float4 b1 = *(float4*)&bs[kk * 128 + n0 + 4];
                    float a[8] = {a0.x, a0.y, a0.z, a0.w, a1.x, a1.y, a1.z, a1.w};
                    float bb[8] = {b0.x, b0.y, b0.z, b0.w, b1.x, b1.y, b1.z, b1.w};
#pragma unroll
                    for (int i = 0; i < 8; i++)
#pragma unroll
                        for (int j = 0; j < 8; j++) acc[i][j] = fmaf(a[i], bb[j], acc[i][j]);
                }
            }
#pragma unroll
            for (int j = 0; j < 8; j++) {
                const float en = g_enorm[kb + n0 + j];
#pragma unroll
                for (int i = 0; i < 8; i++) {
                    float s = fmaf(-2.f, acc[i][j], en);
                    if (s < minv[i]) { minv[i] = s; mini[i] = kb + n0 + j; }
                }
            }
        }
        __syncthreads();
#pragma unroll
        for (int i = 0; i < 8; i++) {
            unsigned int fb = __float_as_uint(minv[i]);
            fb = (fb & 0x80000000u) ? ~fb : (fb | 0x80000000u);
            red[(m0 + i) * 16 + (tid & 15)] = ((unsigned long long)fb << 32) | (unsigned int)mini[i];
        }
        __syncthreads();
        if (tid < 128) {
            unsigned long long m = red[tid * 16];
#pragma unroll
            for (int q = 1; q < 16; q++) {
                unsigned long long v = red[tid * 16 + q];
                if (v < m) m = v;
            }
            g_idx[pl[tid]] = (int)(m & 0xffffffffu);
        }
    }
}

// ---------------- U precompute GEMM ----------------
__global__ __launch_bounds__(256) void ugemm_kernel() {
    __shared__ float as[16 * 128];
    __shared__ float bs[16 * 128];
    const int tid = threadIdx.x;
    const int mb = blockIdx.y * 128;
    const int nb = blockIdx.x * 128;
    const int m0 = (tid >> 4) * 8;
    const int n0 = (tid & 15) * 8;
    const int lr = tid >> 4;
    const int lc = (tid & 15) * 8;

    float acc[8][8];
#pragma unroll
    for (int i = 0; i < 8; i++)
#pragma unroll
        for (int j = 0; j < 8; j++) acc[i][j] = 0.f;

    for (int ks = 0; ks < 8; ks++) {
        const int r = ks * 16 + lr;
        __syncthreads();
        *(float4*)&as[lr * 128 + lc]     = *(const float4*)&g_eT[r * 1024 + mb + lc];
        *(float4*)&as[lr * 128 + lc + 4] = *(const float4*)&g_eT[r * 1024 + mb + lc + 4];
        *(float4*)&bs[lr * 128 + lc]     = *(const float4*)&g_w2t[r * 1152 + nb + lc];
        *(float4*)&bs[lr * 128 + lc + 4] = *(const float4*)&g_w2t[r * 1152 + nb + lc + 4];
        __syncthreads();
#pragma unroll
        for (int kk = 0; kk < 16; kk++) {
            float4 a0 = *(float4*)&as[kk * 128 + m0];
            float4 a1 = *(float4*)&as[kk * 128 + m0 + 4];
            float4 b0 = *(float4*)&bs[kk * 128 + n0];
            float4 b1 = *(float4*)&bs[kk * 128 + n0 + 4];
            float a[8] = {a0.x, a0.y, a0.z, a0.w, a1.x, a1.y, a1.z, a1.w};
            float bb[8] = {b0.x, b0.y, b0.z, b0.w, b1.x, b1.y, b1.z, b1.w};
#pragma unroll
            for (int i = 0; i < 8; i++)
#pragma unroll
                for (int j = 0; j < 8; j++) acc[i][j] = fmaf(a[i], bb[j], acc[i][j]);
        }
    }
#pragma unroll
    for (int i = 0; i < 8; i++) {
        float4 v0, v1;
        v0.x = acc[i][0]; v0.y = acc[i][1]; v0.z = acc[i][2]; v0.w = acc[i][3];
        v1.x = acc[i][4]; v1.y = acc[i][5]; v1.z = acc[i][6]; v1.w = acc[i][7];
        float* dst = &g_U[(size_t)(mb + m0 + i) * 1152 + nb + n0];
        *(float4*)dst = v0;
        *(float4*)(dst + 4) = v1;
    }
}

// ---------------- gather: quant write, loss partials, counts, idx out ----------------
__global__ __launch_bounds__(256) void gather_kernel(const float* __restrict__ emb,
                                                     float* __restrict__ out) {
    __shared__ float qs[64 * 132];
    __shared__ int sc[64];
    __shared__ float lred[8];
    const int tid = threadIdx.x;
    const int pbase = blockIdx.x * 64;
    const int w = tid >> 5, lane = tid & 31;

#pragma unroll
    for (int it = 0; it < 8; it++) {
        const int pl = w * 8 + it;
        const int c = g_idx[pbase + pl];
        float4 v = *(const float4*)&emb[c * 128 + lane * 4];
        *(float4*)&qs[pl * 132 + lane * 4] = v;
        if (lane == 0) { sc[pl] = c; atomicAdd(&g_counts[c], 1); }
    }
    __syncthreads();

    const int pl = tid & 63, dg = tid >> 6;
    const int p = pbase + pl;
    const int b = p >> 12, hw = p & 4095;
    float lsum = 0.f;
#pragma unroll
    for (int dd = 0; dd < 32; dd++) {
        const int d = dg * 32 + dd;
        const float q = qs[pl * 132 + d];
        const float x = g_xT[(size_t)d * NPIX + p];
        const float df = q - x;
        lsum = fmaf(df, df, lsum);
        out[Q_OFF + b * (128 * HW) + d * HW + hw] = q;
    }
#pragma unroll
    for (int off = 16; off > 0; off >>= 1) lsum += __shfl_down_sync(0xffffffffu, lsum, off);
    if (lane == 0) lred[w] = lsum;
    __syncthreads();
    if (tid == 0) {
        float s = 0.f;
        for (int i = 0; i < 8; i++) s += lred[i];
        g_lpart[blockIdx.x] = s;
    }
    if (tid < 64) out[IDX_OFF + pbase + tid] = (float)sc[tid];
}

// ---------------- conv2 via U table ----------------
__global__ __launch_bounds__(256) void conv2_kernel(const float* __restrict__ bias,
                                                    float* __restrict__ out) {
    __shared__ int nid[3][66];
    const int tid = threadIdx.x;
    const int y = blockIdx.x, b = blockIdx.y;
    if (tid < 198) {
        const int r = tid / 66, xi = tid % 66 - 1;
        const int yy = y + r - 1;
        int v = -1;
        if (yy >= 0 && yy < 64 && xi >= 0 && xi < 64) v = g_idx[b * HW + yy * 64 + xi];
        nid[r][tid % 66] = v;
    }
    __syncthreads();

    const int x = tid & 63, og = tid >> 6;
    const int ob = og * 32;
    float acc[32];
#pragma unroll
    for (int u = 0; u < 32; u++) acc[u] = bias[ob + u];

#pragma unroll
    for (int ky = 0; ky < 3; ky++)
#pragma unroll
        for (int kx = 0; kx < 3; kx++) {
            const int c = nid[ky][x + kx];
            if (c >= 0) {
                const float4* Up = (const float4*)&g_U[(size_t)c * 1152 + (ky * 3 + kx) * 128 + ob];
#pragma unroll
                for (int u4 = 0; u4 < 8; u4++) {
                    float4 v = Up[u4];
                    acc[u4 * 4 + 0] += v.x; acc[u4 * 4 + 1] += v.y;
                    acc[u4 * 4 + 2] += v.z; acc[u4 * 4 + 3] += v.w;
                }
            }
        }
    const int base = NV_OFF + b * (128 * HW) + y * 64 + x;
#pragma unroll
    for (int u = 0; u < 32; u++) out[base + (ob + u) * HW] = acc[u];
}

// ---------------- finalize ----------------
__global__ void finalize_kernel(float* __restrict__ out) {
    __shared__ double ds[256];
    __shared__ float hs[256];
    const int t = threadIdx.x;
    double s = 0.0;
    float h = 0.f;
    for (int k = t; k < 1024; k += 256) {
        s += (double)g_lpart[k];
        const float avg = (float)g_counts[k] * (1.0f / 65536.0f);
        h += avg * logf(avg + 1e-10f);
    }
    ds[t] = s; hs[t] = h;
    __syncthreads();
    for (int off = 128; off > 0; off >>= 1) {
        if (t < off) { ds[t] += ds[t + off]; hs[t] += hs[t + off]; }
        __syncthreads();
    }
    if (t == 0) {
        out[0] = (float)(1.25 * ds[0] / 8388608.0);
        out[PERP_OFF] = expf(-hs[0]);
    }
}

// ---------------- launch (conv1 is 4th: profiled slot this round) ----------------
extern "C" void kernel_launch(void* const* d_in, const int* in_sizes, int n_in,
                              void* d_out, int out_size) {
    const float* in  = (const float*)d_in[0];
    const float* w1  = (const float*)d_in[1];
    const float* b1  = (const float*)d_in[2];
    const float* emb = (const float*)d_in[3];
    const float* w2  = (const float*)d_in[4];
    const float* b2  = (const float*)d_in[5];
    float* out = (float*)d_out;

    cudaFuncSetAttribute(screen_kernel, cudaFuncAttributeMaxDynamicSharedMemorySize, SCREEN_SMEM);
    cudaFuncSetAttribute(fb_kernel, cudaFuncAttributeMaxDynamicSharedMemorySize, 74240);

    prep_kernel<<<576, 256>>>(emb, w1, w2);
    prep2_kernel<<<1, 256>>>();
    ugemm_kernel<<<dim3(9, 8), 256>>>();
    conv1_kernel<<<dim3(32, 16), 256>>>(in, b1);
    screen_kernel<<<1024, 512, SCREEN_SMEM>>>();
    merge_kernel<<<256, 256>>>();
    fb_kernel<<<64, 256, 74240>>>();
    gather_kernel<<<1024, 256>>>(emb, out);
    conv2_kernel<<<dim3(64, 16), 256>>>(b2, out);
    finalize_kernel<<<1, 256>>>(out);
}

// round 10
// speedup vs baseline: 1.3946x; 1.2149x over previous
#include <cuda_runtime.h>
#include <cuda_fp16.h>
#include <math.h>
#include <stdint.h>

#define NPIX   65536
#define HW     4096

#define Q_OFF    1
#define NV_OFF   8388609
#define PERP_OFF 16777217
#define IDX_OFF  16777218

// ---------------- scratch (static device arrays; no allocations) ----------------
__device__ float g_xT[128 * NPIX];       // conv1 output, transposed [d][p] (32 MB)
__device__ float g_eT[128 * 1024];       // emb transposed [d][k]
__device__ float g_enorm[1024];          // ||e_k||^2
__device__ float g_w1t[128 * 128];
__device__ float g_w2t[128 * 1152];
__device__ float g_U[1024 * 1152];
__device__ int   g_idx[NPIX];
__device__ int   g_counts[1024];
__device__ float g_lpart[1024];
__device__ float g_xnorm[NPIX];
__device__ float g_score[NPIX];          // chosen-code score (enorm - 2 x.e)
__device__ unsigned long long g_fbkey[NPIX];
__device__ float g_emax;
__device__ int   g_fbcount;
__device__ int   g_fblist[NPIX];
__device__ float g_sm1[2 * NPIX];
__device__ int   g_si1[2 * NPIX];
__device__ float g_sm2[2 * NPIX];
__device__ __align__(16) __half g_x16[NPIX * 128];   // x fp16, row-major [p][d]
__device__ __align__(16) __half g_e16[1024 * 128];   // e fp16, row-major [k][d]

// ---------------- warp MMA helpers (baseline PTX, sm_80+) ----------------
__device__ __forceinline__ uint32_t smem_to_u32(const void* p) {
    uint32_t a;
    asm("{ .reg .u64 t; cvta.to.shared.u64 t, %1; cvt.u32.u64 %0, t; }" : "=r"(a) : "l"(p));
    return a;
}
__device__ __forceinline__ void ldsm_x4(uint32_t& r0, uint32_t& r1, uint32_t& r2, uint32_t& r3, uint32_t addr) {
    asm volatile("ldmatrix.sync.aligned.m8n8.x4.shared.b16 {%0,%1,%2,%3}, [%4];"
                 : "=r"(r0), "=r"(r1), "=r"(r2), "=r"(r3) : "r"(addr));
}
__device__ __forceinline__ void mma16816(float* c, const uint32_t* a, const uint32_t* b) {
    asm volatile("mma.sync.aligned.m16n8k16.row.col.f32.f16.f16.f32 "
                 "{%0,%1,%2,%3}, {%4,%5,%6,%7}, {%8,%9}, {%0,%1,%2,%3};"
                 : "+f"(c[0]), "+f"(c[1]), "+f"(c[2]), "+f"(c[3])
                 : "r"(a[0]), "r"(a[1]), "r"(a[2]), "r"(a[3]), "r"(b[0]), "r"(b[1]));
}
__device__ __forceinline__ void cp_async16(uint32_t smem_addr, const void* gptr) {
    asm volatile("cp.async.cg.shared.global [%0], [%1], 16;" :: "r"(smem_addr), "l"(gptr));
}
#define CP_COMMIT() asm volatile("cp.async.commit_group;" ::: "memory")
#define CP_WAIT0()  asm volatile("cp.async.wait_group 0;" ::: "memory")

// ---------------- prep ----------------
__global__ void prep_kernel(const float* __restrict__ emb,
                            const float* __restrict__ w1,
                            const float* __restrict__ w2) {
    int t = blockIdx.x * blockDim.x + threadIdx.x;
    if (t < 131072) {
        int k = t >> 7, d = t & 127;
        float v = emb[t];
        g_eT[d * 1024 + k] = v;
        g_e16[t] = __float2half_rn(v);
    }
    if (t < 16384)  { int d = t >> 7, c = t & 127; g_w1t[c * 128 + d] = w1[t]; }
    if (t < 147456) {
        int o = t / 1152; int r = t - o * 1152; int i = r / 9, j = r - i * 9;
        g_w2t[i * 1152 + j * 128 + o] = w2[t];
    }
    if (t < 1024) {
        const float* e = emb + t * 128;
        float s = 0.f;
        for (int d = 0; d < 128; d++) s = fmaf(e[d], e[d], s);
        g_enorm[t] = s;
        g_counts[t] = 0;
    }
}

__global__ void prep2_kernel() {
    __shared__ float mx[256];
    const int t = threadIdx.x;
    float m = 0.f;
    for (int k = t; k < 1024; k += 256) m = fmaxf(m, g_enorm[k]);
    mx[t] = m;
    __syncthreads();
    for (int off = 128; off > 0; off >>= 1) {
        if (t < off) mx[t] = fmaxf(mx[t], mx[t + off]);
        __syncthreads();
    }
    if (t == 0) { g_emax = sqrtf(mx[0]); g_fbcount = 0; }
}

// ---------------- conv1: SGEMM + fused fp16 conversion + per-pixel norms ----------------
__global__ __launch_bounds__(256) void conv1_kernel(const float* __restrict__ in,
                                                    const float* __restrict__ bias) {
    __shared__ float as[16 * 128];
    __shared__ float bs[16 * 128];
    __shared__ float pn[128][17];
    const int tid = threadIdx.x;
    const int b   = blockIdx.y;
    const int hwb = blockIdx.x * 128;
    const int m0  = (tid >> 4) * 8;
    const int n0  = (tid & 15) * 8;
    const int lr  = tid >> 4;
    const int lc  = (tid & 15) * 8;
    const float* B = in + b * (128 * HW);

    float acc[8][8];
#pragma unroll
    for (int i = 0; i < 8; i++)
#pragma unroll
        for (int j = 0; j < 8; j++) acc[i][j] = 0.f;

    for (int ks = 0; ks < 8; ks++) {
        const int c0 = ks * 16 + lr;
        __syncthreads();
        *(float4*)&as[lr * 128 + lc]     = *(const float4*)&g_w1t[c0 * 128 + lc];
        *(float4*)&as[lr * 128 + lc + 4] = *(const float4*)&g_w1t[c0 * 128 + lc + 4];
        *(float4*)&bs[lr * 128 + lc]     = *(const float4*)&B[c0 * HW + hwb + lc];
        *(float4*)&bs[lr * 128 + lc + 4] = *(const float4*)&B[c0 * HW + hwb + lc + 4];
        __syncthreads();
#pragma unroll
        for (int kk = 0; kk < 16; kk++) {
            float4 a0 = *(float4*)&as[kk * 128 + m0];
            float4 a1 = *(float4*)&as[kk * 128 + m0 + 4];
            float4 b0 = *(float4*)&bs[kk * 128 + n0];
            float4 b1 = *(float4*)&bs[kk * 128 + n0 + 4];
            float a[8] = {a0.x, a0.y, a0.z, a0.w, a1.x, a1.y, a1.z, a1.w};
            float bb[8] = {b0.x, b0.y, b0.z, b0.w, b1.x, b1.y, b1.z, b1.w};
#pragma unroll
            for (int i = 0; i < 8; i++)
#pragma unroll
                for (int j = 0; j < 8; j++) acc[i][j] = fmaf(a[i], bb[j], acc[i][j]);
        }
    }
#pragma unroll
    for (int i = 0; i < 8; i++) {
        const float bv = bias[m0 + i];
#pragma unroll
        for (int j = 0; j < 8; j++) acc[i][j] += bv;
    }
#pragma unroll
    for (int i = 0; i < 8; i++) {
        float4 v0, v1;
        v0.x = acc[i][0]; v0.y = acc[i][1]; v0.z = acc[i][2]; v0.w = acc[i][3];
        v1.x = acc[i][4]; v1.y = acc[i][5]; v1.z = acc[i][6]; v1.w = acc[i][7];
        float* dst = &g_xT[(size_t)(m0 + i) * NPIX + b * HW + hwb + n0];
        *(float4*)dst = v0;
        *(float4*)(dst + 4) = v1;
    }
#pragma unroll
    for (int j = 0; j < 8; j++) {
        const int p = b * HW + hwb + n0 + j;
        __half h[8];
#pragma unroll
        for (int i = 0; i < 8; i++) h[i] = __float2half_rn(acc[i][j]);
        *(uint4*)&g_x16[(size_t)p * 128 + m0] = *(uint4*)h;
    }
#pragma unroll
    for (int j = 0; j < 8; j++) {
        float s = 0.f;
#pragma unroll
        for (int i = 0; i < 8; i++) s = fmaf(acc[i][j], acc[i][j], s);
        pn[n0 + j][tid >> 4] = s;
    }
    __syncthreads();
    if (tid < 128) {
        float s = 0.f;
#pragma unroll
        for (int g = 0; g < 16; g++) s += pn[tid][g];
        g_xnorm[b * HW + hwb + tid] = sqrtf(s);
    }
}

// ---------------- screen: fp16 mma.sync, pipelined ldsm + cp.async ----------------
#define PITCH  136
#define ES0    34816
#define ES1    69632
#define EN_OFF 104448
#define SCREEN_SMEM 106496

__global__ __launch_bounds__(512, 1) void screen_kernel() {
    extern __shared__ char smc[];
    const uint32_t smb = smem_to_u32(smc);
    const int tid = threadIdx.x;
    const int lane = tid & 31, wid = tid >> 5;
    const int wm = wid >> 2, wn = wid & 3;       // 4 x 4 warp grid; warp tile 32 x 32
    const int pt = blockIdx.x >> 1;
    const int ch = blockIdx.x & 1;
    const int pbase = pt * 128;

#pragma unroll
    for (int j = 0; j < 4; j++) {
        const int id = j * 512 + tid, r = id >> 4, c = id & 15;
        cp_async16(smb + (uint32_t)(r * PITCH + c * 8) * 2,
                   (const char*)g_x16 + (size_t)(pbase + r) * 256 + c * 16);
    }
#pragma unroll
    for (int j = 0; j < 4; j++) {
        const int id = j * 512 + tid, r = id >> 4, c = id & 15;
        cp_async16(smb + ES0 + (uint32_t)(r * PITCH + c * 8) * 2,
                   (const char*)g_e16 + (size_t)(ch * 4) * 32768 + r * 256 + c * 16);
    }
    if (tid < 128) *(float4*)(smc + EN_OFF + tid * 16) = *(const float4*)&g_enorm[ch * 512 + tid * 4];
    CP_COMMIT();
    CP_WAIT0();
    __syncthreads();

    const float* ensm = (const float*)(smc + EN_OFF);
    float mn1[4], mn2[4]; int mi1[4];
#pragma unroll
    for (int s = 0; s < 4; s++) { mn1[s] = 3.4e38f; mn2[s] = 3.4e38f; mi1[s] = 0; }

    const uint32_t a_row = (uint32_t)(wm * 32 + (lane & 15));
    const uint32_t a_koff = (uint32_t)((lane >> 4) << 3);
    const uint32_t b_row = (uint32_t)(wn * 32 + ((lane >> 4) << 3) + (lane & 7));
    const uint32_t b_koff = (uint32_t)(((lane >> 3) & 1) << 3);

    for (int nt = 0; nt < 4; nt++) {
        const int ebase = (nt & 1) ? ES1 : ES0;
        float acc[2][4][4];
#pragma unroll
        for (int mt = 0; mt < 2; mt++)
#pragma unroll
            for (int ntl = 0; ntl < 4; ntl++)
#pragma unroll
                for (int c = 0; c < 4; c++) acc[mt][ntl][c] = 0.f;

        if (nt < 3) {
            const char* src = (const char*)g_e16 + (size_t)(ch * 4 + nt + 1) * 32768;
            const uint32_t dst = smb + ((nt & 1) ? ES0 : ES1);
#pragma unroll
            for (int j = 0; j < 4; j++) {
                const int id = j * 512 + tid, r = id >> 4, c = id & 15;
                cp_async16(dst + (uint32_t)(r * PITCH + c * 8) * 2, src + r * 256 + c * 16);
            }
            CP_COMMIT();
        }

        uint32_t a[2][2][4], b[2][4][2];
        {
#pragma unroll
            for (int mt = 0; mt < 2; mt++) {
                const uint32_t addr = smb + ((a_row + mt * 16) * PITCH + a_koff) * 2;
                ldsm_x4(a[0][mt][0], a[0][mt][1], a[0][mt][2], a[0][mt][3], addr);
            }
#pragma unroll
            for (int nb = 0; nb < 2; nb++) {
                uint32_t r0, r1, r2, r3;
                const uint32_t addr = smb + ebase + ((b_row + nb * 16) * PITCH + b_koff) * 2;
                ldsm_x4(r0, r1, r2, r3, addr);
                b[0][nb * 2][0] = r0; b[0][nb * 2][1] = r1;
                b[0][nb * 2 + 1][0] = r2; b[0][nb * 2 + 1][1] = r3;
            }
        }
#pragma unroll
        for (int kk = 0; kk < 8; kk++) {
            const int cur = kk & 1, nxt = cur ^ 1;
            if (kk < 7) {
                const int k2 = (kk + 1) * 16;
#pragma unroll
                for (int mt = 0; mt < 2; mt++) {
                    const uint32_t addr = smb + ((a_row + mt * 16) * PITCH + k2 + a_koff) * 2;
                    ldsm_x4(a[nxt][mt][0], a[nxt][mt][1], a[nxt][mt][2], a[nxt][mt][3], addr);
                }
#pragma unroll
                for (int nb = 0; nb < 2; nb++) {
                    uint32_t r0, r1, r2, r3;
                    const uint32_t addr = smb + ebase + ((b_row + nb * 16) * PITCH + k2 + b_koff) * 2;
                    ldsm_x4(r0, r1, r2, r3, addr);
                    b[nxt][nb * 2][0] = r0; b[nxt][nb * 2][1] = r1;
                    b[nxt][nb * 2 + 1][0] = r2; b[nxt][nb * 2 + 1][1] = r3;
                }
            }
#pragma unroll
            for (int mt = 0; mt < 2; mt++)
#pragma unroll
                for (int ntl = 0; ntl < 4; ntl++) mma16816(acc[mt][ntl], a[cur][mt], b[cur][ntl]);
        }
#pragma unroll
        for (int mt = 0; mt < 2; mt++)
#pragma unroll
            for (int c = 0; c < 4; c++) {
                const int slot = mt * 2 + (c >> 1);
#pragma unroll
                for (int ntl = 0; ntl < 4; ntl++) {
                    const int col = nt * 128 + wn * 32 + ntl * 8 + ((lane & 3) << 1) + (c & 1);
                    const float s = fmaf(-2.f, acc[mt][ntl][c], ensm[col]);
                    if (s < mn1[slot]) { mn2[slot] = mn1[slot]; mn1[slot] = s; mi1[slot] = col; }
                    else if (s < mn2[slot]) mn2[slot] = s;
                }
            }
        if (nt < 3) CP_WAIT0();
        __syncthreads();
    }

#pragma unroll
    for (int s = 0; s < 4; s++) {
#pragma unroll
        for (int m = 1; m <= 2; m <<= 1) {
            const float o1 = __shfl_xor_sync(0xffffffffu, mn1[s], m);
            const float o2 = __shfl_xor_sync(0xffffffffu, mn2[s], m);
            const int   oi = __shfl_xor_sync(0xffffffffu, mi1[s], m);
            if (o1 < mn1[s]) { mn2[s] = fminf(mn1[s], o2); mn1[s] = o1; mi1[s] = oi; }
            else mn2[s] = fminf(mn2[s], o1);
        }
    }
    float* f1 = (float*)smc;
    int*   j1 = (int*)(smc + 2048);
    float* f2 = (float*)(smc + 4096);
    if ((lane & 3) == 0) {
#pragma unroll
        for (int s = 0; s < 4; s++) {
            const int row = wm * 32 + (s >> 1) * 16 + (s & 1) * 8 + (lane >> 2);
            f1[row * 4 + wn] = mn1[s];
            j1[row * 4 + wn] = mi1[s];
            f2[row * 4 + wn] = mn2[s];
        }
    }
    __syncthreads();
    if (tid < 128) {
        float m1 = f1[tid * 4], m2 = f2[tid * 4];
        int i1 = j1[tid * 4];
#pragma unroll
        for (int w = 1; w < 4; w++) {
            const float o1 = f1[tid * 4 + w], o2 = f2[tid * 4 + w];
            const int oi = j1[tid * 4 + w];
            if (o1 < m1) { m2 = fminf(m1, o2); m1 = o1; i1 = oi; }
            else m2 = fminf(m2, o1);
        }
        const int p = pbase + tid;
        g_sm1[ch * NPIX + p] = m1;
        g_si1[ch * NPIX + p] = ch * 512 + i1;
        g_sm2[ch * NPIX + p] = m2;
    }
}

// ---------------- merge halves + margin test ----------------
__global__ __launch_bounds__(256) void merge_kernel() {
    const int p = blockIdx.x * blockDim.x + threadIdx.x;
    const float a1 = g_sm1[p], b1 = g_sm1[NPIX + p];
    const float a2 = g_sm2[p], b2 = g_sm2[NPIX + p];
    const int ia = g_si1[p], ib = g_si1[NPIX + p];
    float m1, m2; int i1;
    if (a1 < b1 || (a1 == b1 && ia < ib)) { m1 = a1; i1 = ia; m2 = fminf(a2, b1); }
    else { m1 = b1; i1 = ib; m2 = fminf(b2, a1); }
    g_idx[p] = i1;
    g_score[p] = m1;
    const float thresh = fmaf(4.5e-3f * g_emax, g_xnorm[p], 1e-5f);
    if (m2 - m1 <= thresh) {
        g_fbkey[p] = 0xFFFFFFFFFFFFFFFFull;
        const int pos = atomicAdd(&g_fbcount, 1);
        g_fblist[pos] = p;
    }
}

// ---------------- full fallback: 4-way code-split exact fp32 argmin ----------------
__global__ __launch_bounds__(256) void fb_kernel() {
    extern __shared__ float sm[];
    float* xs = sm;                                      // [128d][128px] 64 KB
    float* bs = sm + 16384;
    int*   pl = (int*)(sm + 18432);
    unsigned long long* red = (unsigned long long*)sm;   // aliases xs post-compute

    const int tid = threadIdx.x;
    const int cnt = g_fbcount;
    const int nunits = ((cnt + 127) >> 7) << 2;          // 4 code-quarters per tile

    for (int u = blockIdx.x; u < nunits; u += gridDim.x) {
        const int t = u >> 2, cq = u & 3;
        __syncthreads();
        if (tid < 128) {
            const int li = t * 128 + tid;
            pl[tid] = (li < cnt) ? g_fblist[li] : g_fblist[0];
        }
        __syncthreads();
        {
            const int i = tid & 127;
            const int p = pl[i];
#pragma unroll 4
            for (int j = 0; j < 64; j++) {
                const int d = (tid >> 7) + j * 2;
                xs[d * 128 + i] = g_xT[(size_t)d * NPIX + p];
            }
        }
        __syncthreads();

        const int m0 = (tid >> 4) * 8;
        const int n0 = (tid & 15) * 8;
        const int lr = tid >> 4;
        const int lc = (tid & 15) * 8;

        float minv[8]; int mini[8];
#pragma unroll
        for (int i = 0; i < 8; i++) { minv[i] = 3.4e38f; mini[i] = 0; }

        for (int nt = 0; nt < 2; nt++) {
            const int kb = cq * 256 + nt * 128;
            float acc[8][8];
#pragma unroll
            for (int i = 0; i < 8; i++)
#pragma unroll
                for (int j = 0; j < 8; j++) acc[i][j] = 0.f;

            for (int ks = 0; ks < 8; ks++) {
                const int r = ks * 16 + lr;
                __syncthreads();
                *(float4*)&bs[lr * 128 + lc]     = *(const float4*)&g_eT[r * 1024 + kb + lc];
                *(float4*)&bs[lr * 128 + lc + 4] = *(const float4*)&g_eT[r * 1024 + kb + lc + 4];
                __syncthreads();
#pragma unroll
                for (int kk = 0; kk < 16; kk++) {
                    const int dd = ks * 16 + kk;
                    float4 a0 = *(float4*)&xs[dd * 128 + m0];
                    float4 a1 = *(float4*)&xs[dd * 128 + m0 + 4];
                    float4 b0 = *(float4*)&bs[kk * 128 + n0];
                    float4 b1 = *(float4*)&bs[kk * 128 + n0 + 4];
                    float a[8] = {a0.x, a0.y, a0.z, a0.w, a1.x, a1.y, a1.z, a1.w};
                    float bb[8] = {b0.x, b0.y, b0.z, b0.w, b1.x, b1.y, b1.z, b1.w};
#pragma unroll
                    for (int i = 0; i < 8; i++)
#pragma unroll
                        for (int j = 0; j < 8; j++) acc[i][j] = fmaf(a[i], bb[j], acc[i][j]);
                }
            }
#pragma unroll
            for (int j = 0; j < 8; j++) {
                const float en = g_enorm[kb + n0 + j];
#pragma unroll
                for (int i = 0; i < 8; i++) {
                    float s = fmaf(-2.f, acc[i][j], en);
                    if (s < minv[i]) { minv[i] = s; mini[i] = kb + n0 + j; }
                }
            }
        }
        __syncthreads();  // xs dead -> red aliases
#pragma unroll
        for (int i = 0; i < 8; i++) {
            unsigned int fb = __float_as_uint(minv[i]);
            fb = (fb & 0x80000000u) ? ~fb : (fb | 0x80000000u);
            red[(m0 + i) * 16 + (tid & 15)] = ((unsigned long long)fb << 32) | (unsigned int)mini[i];
        }
        __syncthreads();
        if (tid < 128) {
            unsigned long long m = red[tid * 16];
#pragma unroll
            for (int q = 1; q < 16; q++) {
                unsigned long long v = red[tid * 16 + q];
                if (v < m) m = v;
            }
            atomicMin(&g_fbkey[pl[tid]], m);
        }
    }
}

// ---------------- fbfix: decode combined keys ----------------
__global__ void fbfix_kernel() {
    const int cnt = g_fbcount;
    for (int i = blockIdx.x * blockDim.x + threadIdx.x; i < cnt; i += gridDim.x * blockDim.x) {
        const int p = g_fblist[i];
        const unsigned long long k = g_fbkey[p];
        const unsigned int fb = (unsigned int)(k >> 32);
        const unsigned int bits = (fb & 0x80000000u) ? (fb & 0x7fffffffu) : ~fb;
        g_idx[p] = (int)(k & 0xffffffffu);
        g_score[p] = __uint_as_float(bits);
    }
}

// ---------------- gather: quant write, loss via score identity, counts, idx out ----------------
__global__ __launch_bounds__(256) void gather_kernel(const float* __restrict__ emb,
                                                     float* __restrict__ out) {
    __shared__ float qs[64 * 132];
    __shared__ int sc[64];
    __shared__ float sl[64];
    const int tid = threadIdx.x;
    const int pbase = blockIdx.x * 64;
    const int w = tid >> 5, lane = tid & 31;

#pragma unroll
    for (int it = 0; it < 8; it++) {
        const int pl = w * 8 + it;
        const int c = g_idx[pbase + pl];
        float4 v = *(const float4*)&emb[c * 128 + lane * 4];
        *(float4*)&qs[pl * 132 + lane * 4] = v;
        if (lane == 0) { sc[pl] = c; atomicAdd(&g_counts[c], 1); }
    }
    if (tid < 64) {
        const int p2 = pbase + tid;
        const float xn = g_xnorm[p2];
        sl[tid] = g_score[p2] + xn * xn;   // ||q - x||^2 for this pixel
    }
    __syncthreads();

    const int pl = tid & 63, dg = tid >> 6;
    const int p = pbase + pl;
    const int b = p >> 12, hw = p & 4095;
#pragma unroll
    for (int dd = 0; dd < 32; dd++) {
        const int d = dg * 32 + dd;
        out[Q_OFF + b * (128 * HW) + d * HW + hw] = qs[pl * 132 + d];
    }
    if (tid == 0) {
        float s = 0.f;
        for (int i = 0; i < 64; i++) s += sl[i];
        g_lpart[blockIdx.x] = s;
    }
    if (tid < 64) out[IDX_OFF + pbase + tid] = (float)sc[tid];
}

// ---------------- U precompute GEMM ----------------
__global__ __launch_bounds__(256) void ugemm_kernel() {
    __shared__ float as[16 * 128];
    __shared__ float bs[16 * 128];
    const int tid = threadIdx.x;
    const int mb = blockIdx.y * 128;
    const int nb = blockIdx.x * 128;
    const int m0 = (tid >> 4) * 8;
    const int n0 = (tid & 15) * 8;
    const int lr = tid >> 4;
    const int lc = (tid & 15) * 8;

    float acc[8][8];
#pragma unroll
    for (int i = 0; i < 8; i++)
#pragma unroll
        for (int j = 0; j < 8; j++) acc[i][j] = 0.f;

    for (int ks = 0; ks < 8; ks++) {
        const int r = ks * 16 + lr;
        __syncthreads();
        *(float4*)&as[lr * 128 + lc]     = *(const float4*)&g_eT[r * 1024 + mb + lc];
        *(float4*)&as[lr * 128 + lc + 4] = *(const float4*)&g_eT[r * 1024 + mb + lc + 4];
        *(float4*)&bs[lr * 128 + lc]     = *(const float4*)&g_w2t[r * 1152 + nb + lc];
        *(float4*)&bs[lr * 128 + lc + 4] = *(const float4*)&g_w2t[r * 1152 + nb + lc + 4];
        __syncthreads();
#pragma unroll
        for (int kk = 0; kk < 16; kk++) {
            float4 a0 = *(float4*)&as[kk * 128 + m0];
            float4 a1 = *(float4*)&as[kk * 128 + m0 + 4];
            float4 b0 = *(float4*)&bs[kk * 128 + n0];
            float4 b1 = *(float4*)&bs[kk * 128 + n0 + 4];
            float a[8] = {a0.x, a0.y, a0.z, a0.w, a1.x, a1.y, a1.z, a1.w};
            float bb[8] = {b0.x, b0.y, b0.z, b0.w, b1.x, b1.y, b1.z, b1.w};
#pragma unroll
            for (int i = 0; i < 8; i++)
#pragma unroll
                for (int j = 0; j < 8; j++) acc[i][j] = fmaf(a[i], bb[j], acc[i][j]);
        }
    }
#pragma unroll
    for (int i = 0; i < 8; i++) {
        float4 v0, v1;
        v0.x = acc[i][0]; v0.y = acc[i][1]; v0.z = acc[i][2]; v0.w = acc[i][3];
        v1.x = acc[i][4]; v1.y = acc[i][5]; v1.z = acc[i][6]; v1.w = acc[i][7];
        float* dst = &g_U[(size_t)(mb + m0 + i) * 1152 + nb + n0];
        *(float4*)dst = v0;
        *(float4*)(dst + 4) = v1;
    }
}

// ---------------- conv2 via U table ----------------
__global__ __launch_bounds__(256) void conv2_kernel(const float* __restrict__ bias,
                                                    float* __restrict__ out) {
    __shared__ int nid[3][66];
    const int tid = threadIdx.x;
    const int y = blockIdx.x, b = blockIdx.y;
    if (tid < 198) {
        const int r = tid / 66, xi = tid % 66 - 1;
        const int yy = y + r - 1;
        int v = -1;
        if (yy >= 0 && yy < 64 && xi >= 0 && xi < 64) v = g_idx[b * HW + yy * 64 + xi];
        nid[r][tid % 66] = v;
    }
    __syncthreads();

    const int x = tid & 63, og = tid >> 6;
    const int ob = og * 32;
    float acc[32];
#pragma unroll
    for (int u = 0; u < 32; u++) acc[u] = bias[ob + u];

#pragma unroll
    for (int ky = 0; ky < 3; ky++)
#pragma unroll
        for (int kx = 0; kx < 3; kx++) {
            const int c = nid[ky][x + kx];
            if (c >= 0) {
                const float4* Up = (const float4*)&g_U[(size_t)c * 1152 + (ky * 3 + kx) * 128 + ob];
#pragma unroll
                for (int u4 = 0; u4 < 8; u4++) {
                    float4 v = Up[u4];
                    acc[u4 * 4 + 0] += v.x; acc[u4 * 4 + 1] += v.y;
                    acc[u4 * 4 + 2] += v.z; acc[u4 * 4 + 3] += v.w;
                }
            }
        }
    const int base = NV_OFF + b * (128 * HW) + y * 64 + x;
#pragma unroll
    for (int u = 0; u < 32; u++) out[base + (ob + u) * HW] = acc[u];
}

// ---------------- finalize ----------------
__global__ void finalize_kernel(float* __restrict__ out) {
    __shared__ double ds[256];
    __shared__ float hs[256];
    const int t = threadIdx.x;
    double s = 0.0;
    float h = 0.f;
    for (int k = t; k < 1024; k += 256) {
        s += (double)g_lpart[k];
        const float avg = (float)g_counts[k] * (1.0f / 65536.0f);
        h += avg * logf(avg + 1e-10f);
    }
    ds[t] = s; hs[t] = h;
    __syncthreads();
    for (int off = 128; off > 0; off >>= 1) {
        if (t < off) { ds[t] += ds[t + off]; hs[t] += hs[t + off]; }
        __syncthreads();
    }
    if (t == 0) {
        out[0] = (float)(1.25 * ds[0] / 8388608.0);
        out[PERP_OFF] = expf(-hs[0]);
    }
}

// ---------------- launch (screen is 4th: profiled slot) ----------------
extern "C" void kernel_launch(void* const* d_in, const int* in_sizes, int n_in,
                              void* d_out, int out_size) {
    const float* in  = (const float*)d_in[0];
    const float* w1  = (const float*)d_in[1];
    const float* b1  = (const float*)d_in[2];
    const float* emb = (const float*)d_in[3];
    const float* w2  = (const float*)d_in[4];
    const float* b2  = (const float*)d_in[5];
    float* out = (float*)d_out;

    cudaFuncSetAttribute(screen_kernel, cudaFuncAttributeMaxDynamicSharedMemorySize, SCREEN_SMEM);
    cudaFuncSetAttribute(fb_kernel, cudaFuncAttributeMaxDynamicSharedMemorySize, 74240);

    prep_kernel<<<576, 256>>>(emb, w1, w2);
    prep2_kernel<<<1, 256>>>();
    conv1_kernel<<<dim3(32, 16), 256>>>(in, b1);
    screen_kernel<<<1024, 512, SCREEN_SMEM>>>();
    merge_kernel<<<256, 256>>>();
    fb_kernel<<<256, 256, 74240>>>();
    fbfix_kernel<<<64, 256>>>();
    ugemm_kernel<<<dim3(9, 8), 256>>>();
    gather_kernel<<<1024, 256>>>(emb, out);
    conv2_kernel<<<dim3(64, 16), 256>>>(b2, out);
    finalize_kernel<<<1, 256>>>(out);
}

// round 11
// speedup vs baseline: 1.4913x; 1.0694x over previous
#include <cuda_runtime.h>
#include <cuda_fp16.h>
#include <math.h>
#include <stdint.h>

#define NPIX   65536
#define HW     4096

#define Q_OFF    1
#define NV_OFF   8388609
#define PERP_OFF 16777217
#define IDX_OFF  16777218

// ---------------- scratch (static device arrays; no allocations) ----------------
__device__ float g_xT[128 * NPIX];       // conv1 output, transposed [d][p] (32 MB)
__device__ float g_eT[128 * 1024];       // emb transposed [d][k]
__device__ float g_enorm[1024];          // ||e_k||^2
__device__ float g_w1t[128 * 128];
__device__ float g_w2t[128 * 1152];
__device__ float g_U[1024 * 1152];
__device__ int   g_idx[NPIX];
__device__ int   g_counts[1024];
__device__ float g_lpart[1024];
__device__ float g_xnorm[NPIX];
__device__ float g_score[NPIX];          // chosen-code score (enorm - 2 x.e)
__device__ unsigned long long g_fbkey[NPIX];
__device__ float g_emax;
__device__ int   g_fbcount;
__device__ int   g_fblist[NPIX];
__device__ float g_sm1[2 * NPIX];
__device__ int   g_si1[2 * NPIX];
__device__ float g_sm2[2 * NPIX];
__device__ __align__(16) __half g_x16[NPIX * 128];   // x fp16, row-major [p][d]
__device__ __align__(16) __half g_e16[1024 * 128];   // e fp16, row-major [k][d]

// ---------------- warp MMA helpers (baseline PTX, sm_80+) ----------------
__device__ __forceinline__ uint32_t smem_to_u32(const void* p) {
    uint32_t a;
    asm("{ .reg .u64 t; cvta.to.shared.u64 t, %1; cvt.u32.u64 %0, t; }" : "=r"(a) : "l"(p));
    return a;
}
__device__ __forceinline__ void ldsm_x4(uint32_t& r0, uint32_t& r1, uint32_t& r2, uint32_t& r3, uint32_t addr) {
    asm volatile("ldmatrix.sync.aligned.m8n8.x4.shared.b16 {%0,%1,%2,%3}, [%4];"
                 : "=r"(r0), "=r"(r1), "=r"(r2), "=r"(r3) : "r"(addr));
}
__device__ __forceinline__ void mma16816(float* c, const uint32_t* a, const uint32_t* b) {
    asm volatile("mma.sync.aligned.m16n8k16.row.col.f32.f16.f16.f32 "
                 "{%0,%1,%2,%3}, {%4,%5,%6,%7}, {%8,%9}, {%0,%1,%2,%3};"
                 : "+f"(c[0]), "+f"(c[1]), "+f"(c[2]), "+f"(c[3])
                 : "r"(a[0]), "r"(a[1]), "r"(a[2]), "r"(a[3]), "r"(b[0]), "r"(b[1]));
}
__device__ __forceinline__ void cp_async16(uint32_t smem_addr, const void* gptr) {
    asm volatile("cp.async.cg.shared.global [%0], [%1], 16;" :: "r"(smem_addr), "l"(gptr));
}
#define CP_COMMIT() asm volatile("cp.async.commit_group;" ::: "memory")
#define CP_WAIT0()  asm volatile("cp.async.wait_group 0;" ::: "memory")

// ---------------- prep ----------------
__global__ void prep_kernel(const float* __restrict__ emb,
                            const float* __restrict__ w1,
                            const float* __restrict__ w2) {
    int t = blockIdx.x * blockDim.x + threadIdx.x;
    if (t < 131072) {
        int k = t >> 7, d = t & 127;
        float v = emb[t];
        g_eT[d * 1024 + k] = v;
        g_e16[t] = __float2half_rn(v);
    }
    if (t < 16384)  { int d = t >> 7, c = t & 127; g_w1t[c * 128 + d] = w1[t]; }
    if (t < 147456) {
        int o = t / 1152; int r = t - o * 1152; int i = r / 9, j = r - i * 9;
        g_w2t[i * 1152 + j * 128 + o] = w2[t];
    }
    if (t < 1024) {
        const float* e = emb + t * 128;
        float s = 0.f;
        for (int d = 0; d < 128; d++) s = fmaf(e[d], e[d], s);
        g_enorm[t] = s;
        g_counts[t] = 0;
    }
}

__global__ void prep2_kernel() {
    __shared__ float mx[256];
    const int t = threadIdx.x;
    float m = 0.f;
    for (int k = t; k < 1024; k += 256) m = fmaxf(m, g_enorm[k]);
    mx[t] = m;
    __syncthreads();
    for (int off = 128; off > 0; off >>= 1) {
        if (t < off) mx[t] = fmaxf(mx[t], mx[t + off]);
        __syncthreads();
    }
    if (t == 0) { g_emax = sqrtf(mx[0]); g_fbcount = 0; }
}

// ---------------- conv1: cp.async double-buffered SGEMM + fused fp16/norm epilogue ----------------
__global__ __launch_bounds__(256) void conv1_kernel(const float* __restrict__ in,
                                                    const float* __restrict__ bias) {
    __shared__ float as[2][16 * 128];
    __shared__ float bs[2][16 * 128];
    __shared__ float pn[128][17];
    const int tid = threadIdx.x;
    const int b   = blockIdx.y;
    const int hwb = blockIdx.x * 128;
    const int m0  = (tid >> 4) * 8;
    const int n0  = (tid & 15) * 8;
    const int lr  = tid >> 4;
    const int lc  = (tid & 15) * 8;
    const float* B = in + b * (128 * HW);
    const uint32_t as_b = smem_to_u32(as);
    const uint32_t bs_b = smem_to_u32(bs);

    float acc[8][8];
#pragma unroll
    for (int i = 0; i < 8; i++)
#pragma unroll
        for (int j = 0; j < 8; j++) acc[i][j] = 0.f;

    // preload ks=0 into buf 0
    {
        const int c0 = lr;
        cp_async16(as_b + (uint32_t)(lr * 128 + lc) * 4,       &g_w1t[c0 * 128 + lc]);
        cp_async16(as_b + (uint32_t)(lr * 128 + lc + 4) * 4,   &g_w1t[c0 * 128 + lc + 4]);
        cp_async16(bs_b + (uint32_t)(lr * 128 + lc) * 4,       &B[c0 * HW + hwb + lc]);
        cp_async16(bs_b + (uint32_t)(lr * 128 + lc + 4) * 4,   &B[c0 * HW + hwb + lc + 4]);
        CP_COMMIT();
    }
    CP_WAIT0();
    __syncthreads();

    for (int ks = 0; ks < 8; ks++) {
        const int cur = ks & 1;
        if (ks < 7) {
            const int nb = (ks + 1) & 1;
            const int c0 = (ks + 1) * 16 + lr;
            const uint32_t off = (uint32_t)(nb * 2048 + lr * 128 + lc) * 4;
            cp_async16(as_b + off,      &g_w1t[c0 * 128 + lc]);
            cp_async16(as_b + off + 16, &g_w1t[c0 * 128 + lc + 4]);
            cp_async16(bs_b + off,      &B[c0 * HW + hwb + lc]);
            cp_async16(bs_b + off + 16, &B[c0 * HW + hwb + lc + 4]);
            CP_COMMIT();
        }
#pragma unroll
        for (int kk = 0; kk < 16; kk++) {
            float4 a0 = *(float4*)&as[cur][kk * 128 + m0];
            float4 a1 = *(float4*)&as[cur][kk * 128 + m0 + 4];
            float4 b0 = *(float4*)&bs[cur][kk * 128 + n0];
            float4 b1 = *(float4*)&bs[cur][kk * 128 + n0 + 4];
            float a[8] = {a0.x, a0.y, a0.z, a0.w, a1.x, a1.y, a1.z, a1.w};
            float bb[8] = {b0.x, b0.y, b0.z, b0.w, b1.x, b1.y, b1.z, b1.w};
#pragma unroll
            for (int i = 0; i < 8; i++)
#pragma unroll
                for (int j = 0; j < 8; j++) acc[i][j] = fmaf(a[i], bb[j], acc[i][j]);
        }
        CP_WAIT0();
        __syncthreads();
    }
#pragma unroll
    for (int i = 0; i < 8; i++) {
        const float bv = bias[m0 + i];
#pragma unroll
        for (int j = 0; j < 8; j++) acc[i][j] += bv;
    }
#pragma unroll
    for (int i = 0; i < 8; i++) {
        float4 v0, v1;
        v0.x = acc[i][0]; v0.y = acc[i][1]; v0.z = acc[i][2]; v0.w = acc[i][3];
        v1.x = acc[i][4]; v1.y = acc[i][5]; v1.z = acc[i][6]; v1.w = acc[i][7];
        float* dst = &g_xT[(size_t)(m0 + i) * NPIX + b * HW + hwb + n0];
        *(float4*)dst = v0;
        *(float4*)(dst + 4) = v1;
    }
#pragma unroll
    for (int j = 0; j < 8; j++) {
        const int p = b * HW + hwb + n0 + j;
        __half h[8];
#pragma unroll
        for (int i = 0; i < 8; i++) h[i] = __float2half_rn(acc[i][j]);
        *(uint4*)&g_x16[(size_t)p * 128 + m0] = *(uint4*)h;
    }
#pragma unroll
    for (int j = 0; j < 8; j++) {
        float s = 0.f;
#pragma unroll
        for (int i = 0; i < 8; i++) s = fmaf(acc[i][j], acc[i][j], s);
        pn[n0 + j][tid >> 4] = s;
    }
    __syncthreads();
    if (tid < 128) {
        float s = 0.f;
#pragma unroll
        for (int g = 0; g < 16; g++) s += pn[tid][g];
        g_xnorm[b * HW + hwb + tid] = sqrtf(s);
    }
}

// ---------------- screen: fp16 mma.sync, 64px x 512 codes, 256 thr, 2 CTAs/SM ----------------
#define PITCH  136
#define ES0    17408
#define ES1    52224
#define EN_OFF 87040
#define SCREEN_SMEM 89088

__global__ __launch_bounds__(256, 2) void screen_kernel() {
    extern __shared__ char smc[];
    const uint32_t smb = smem_to_u32(smc);
    const int tid = threadIdx.x;
    const int lane = tid & 31, wid = tid >> 5;
    const int wm = wid >> 2, wn = wid & 3;       // 2 x 4 warp grid; warp tile 32 x 32
    const int pt = blockIdx.x >> 1;
    const int ch = blockIdx.x & 1;
    const int pbase = pt * 64;

    // x tile (64 rows x 128 d)
#pragma unroll
    for (int j = 0; j < 4; j++) {
        const int id = j * 256 + tid, r = id >> 4, c = id & 15;
        cp_async16(smb + (uint32_t)(r * PITCH + c * 8) * 2,
                   (const char*)g_x16 + (size_t)(pbase + r) * 256 + c * 16);
    }
    // e tile 0 (128 rows)
#pragma unroll
    for (int j = 0; j < 8; j++) {
        const int id = j * 256 + tid, r = id >> 4, c = id & 15;
        cp_async16(smb + ES0 + (uint32_t)(r * PITCH + c * 8) * 2,
                   (const char*)g_e16 + (size_t)(ch * 4) * 32768 + r * 256 + c * 16);
    }
    if (tid < 128) *(float4*)(smc + EN_OFF + tid * 16) = *(const float4*)&g_enorm[ch * 512 + tid * 4];
    CP_COMMIT();
    CP_WAIT0();
    __syncthreads();

    const float* ensm = (const float*)(smc + EN_OFF);
    float mn1[4], mn2[4]; int mi1[4];
#pragma unroll
    for (int s = 0; s < 4; s++) { mn1[s] = 3.4e38f; mn2[s] = 3.4e38f; mi1[s] = 0; }

    const uint32_t a_row = (uint32_t)(wm * 32 + (lane & 15));
    const uint32_t a_koff = (uint32_t)((lane >> 4) << 3);
    const uint32_t b_row = (uint32_t)(wn * 32 + ((lane >> 4) << 3) + (lane & 7));
    const uint32_t b_koff = (uint32_t)(((lane >> 3) & 1) << 3);

    for (int nt = 0; nt < 4; nt++) {
        const int ebase = (nt & 1) ? ES1 : ES0;
        float acc[2][4][4];
#pragma unroll
        for (int mt = 0; mt < 2; mt++)
#pragma unroll
            for (int ntl = 0; ntl < 4; ntl++)
#pragma unroll
                for (int c = 0; c < 4; c++) acc[mt][ntl][c] = 0.f;

        if (nt < 3) {
            const char* src = (const char*)g_e16 + (size_t)(ch * 4 + nt + 1) * 32768;
            const uint32_t dst = smb + ((nt & 1) ? ES0 : ES1);
#pragma unroll
            for (int j = 0; j < 8; j++) {
                const int id = j * 256 + tid, r = id >> 4, c = id & 15;
                cp_async16(dst + (uint32_t)(r * PITCH + c * 8) * 2, src + r * 256 + c * 16);
            }
            CP_COMMIT();
        }

        uint32_t a[2][2][4], b[2][4][2];
        {
#pragma unroll
            for (int mt = 0; mt < 2; mt++) {
                const uint32_t addr = smb + ((a_row + mt * 16) * PITCH + a_koff) * 2;
                ldsm_x4(a[0][mt][0], a[0][mt][1], a[0][mt][2], a[0][mt][3], addr);
            }
#pragma unroll
            for (int nb = 0; nb < 2; nb++) {
                uint32_t r0, r1, r2, r3;
                const uint32_t addr = smb + ebase + ((b_row + nb * 16) * PITCH + b_koff) * 2;
                ldsm_x4(r0, r1, r2, r3, addr);
                b[0][nb * 2][0] = r0; b[0][nb * 2][1] = r1;
                b[0][nb * 2 + 1][0] = r2; b[0][nb * 2 + 1][1] = r3;
            }
        }
#pragma unroll
        for (int kk = 0; kk < 8; kk++) {
            const int cur = kk & 1, nxt = cur ^ 1;
            if (kk < 7) {
                const int k2 = (kk + 1) * 16;
#pragma unroll
                for (int mt = 0; mt < 2; mt++) {
                    const uint32_t addr = smb + ((a_row + mt * 16) * PITCH + k2 + a_koff) * 2;
                    ldsm_x4(a[nxt][mt][0], a[nxt][mt][1], a[nxt][mt][2], a[nxt][mt][3], addr);
                }
#pragma unroll
                for (int nb = 0; nb < 2; nb++) {
                    uint32_t r0, r1, r2, r3;
                    const uint32_t addr = smb + ebase + ((b_row + nb * 16) * PITCH + k2 + b_koff) * 2;
                    ldsm_x4(r0, r1, r2, r3, addr);
                    b[nxt][nb * 2][0] = r0; b[nxt][nb * 2][1] = r1;
                    b[nxt][nb * 2 + 1][0] = r2; b[nxt][nb * 2 + 1][1] = r3;
                }
            }
#pragma unroll
            for (int mt = 0; mt < 2; mt++)
#pragma unroll
                for (int ntl = 0; ntl < 4; ntl++) mma16816(acc[mt][ntl], a[cur][mt], b[cur][ntl]);
        }
#pragma unroll
        for (int mt = 0; mt < 2; mt++)
#pragma unroll
            for (int c = 0; c < 4; c++) {
                const int slot = mt * 2 + (c >> 1);
#pragma unroll
                for (int ntl = 0; ntl < 4; ntl++) {
                    const int col = nt * 128 + wn * 32 + ntl * 8 + ((lane & 3) << 1) + (c & 1);
                    const float s = fmaf(-2.f, acc[mt][ntl][c], ensm[col]);
                    if (s < mn1[slot]) { mn2[slot] = mn1[slot]; mn1[slot] = s; mi1[slot] = col; }
                    else if (s < mn2[slot]) mn2[slot] = s;
                }
            }
        if (nt < 3) CP_WAIT0();
        __syncthreads();
    }

    // in-warp merge across the 4 lanes sharing each row (lane&3 partitions cols)
#pragma unroll
    for (int s = 0; s < 4; s++) {
#pragma unroll
        for (int m = 1; m <= 2; m <<= 1) {
            const float o1 = __shfl_xor_sync(0xffffffffu, mn1[s], m);
            const float o2 = __shfl_xor_sync(0xffffffffu, mn2[s], m);
            const int   oi = __shfl_xor_sync(0xffffffffu, mi1[s], m);
            if (o1 < mn1[s]) { mn2[s] = fminf(mn1[s], o2); mn1[s] = o1; mi1[s] = oi; }
            else mn2[s] = fminf(mn2[s], o1);
        }
    }
    // cross-warp merge via smem (x region dead: 3 KB < 17 KB)
    float* f1 = (float*)smc;
    int*   j1 = (int*)(smc + 1024);
    float* f2 = (float*)(smc + 2048);
    if ((lane & 3) == 0) {
#pragma unroll
        for (int s = 0; s < 4; s++) {
            const int row = wm * 32 + (s >> 1) * 16 + (s & 1) * 8 + (lane >> 2);
            f1[row * 4 + wn] = mn1[s];
            j1[row * 4 + wn] = mi1[s];
            f2[row * 4 + wn] = mn2[s];
        }
    }
    __syncthreads();
    if (tid < 64) {
        float m1 = f1[tid * 4], m2 = f2[tid * 4];
        int i1 = j1[tid * 4];
#pragma unroll
        for (int w = 1; w < 4; w++) {
            const float o1 = f1[tid * 4 + w], o2 = f2[tid * 4 + w];
            const int oi = j1[tid * 4 + w];
            if (o1 < m1) { m2 = fminf(m1, o2); m1 = o1; i1 = oi; }
            else m2 = fminf(m2, o1);
        }
        const int p = pbase + tid;
        g_sm1[ch * NPIX + p] = m1;
        g_si1[ch * NPIX + p] = ch * 512 + i1;
        g_sm2[ch * NPIX + p] = m2;
    }
}

// ---------------- merge halves + margin test ----------------
__global__ __launch_bounds__(256) void merge_kernel() {
    const int p = blockIdx.x * blockDim.x + threadIdx.x;
    const float a1 = g_sm1[p], b1 = g_sm1[NPIX + p];
    const float a2 = g_sm2[p], b2 = g_sm2[NPIX + p];
    const int ia = g_si1[p], ib = g_si1[NPIX + p];
    float m1, m2; int i1;
    if (a1 < b1 || (a1 == b1 && ia < ib)) { m1 = a1; i1 = ia; m2 = fminf(a2, b1); }
    else { m1 = b1; i1 = ib; m2 = fminf(b2, a1); }
    g_idx[p] = i1;
    g_score[p] = m1;
    const float thresh = fmaf(4.5e-3f * g_emax, g_xnorm[p], 1e-5f);
    if (m2 - m1 <= thresh) {
        g_fbkey[p] = 0xFFFFFFFFFFFFFFFFull;
        const int pos = atomicAdd(&g_fbcount, 1);
        g_fblist[pos] = p;
    }
}

// ---------------- full fallback: 4-way code-split exact fp32 argmin ----------------
__global__ __launch_bounds__(256) void fb_kernel() {
    extern __shared__ float sm[];
    float* xs = sm;                                      // [128d][128px] 64 KB
    float* bs = sm + 16384;
    int*   pl = (int*)(sm + 18432);
    unsigned long long* red = (unsigned long long*)sm;   // aliases xs post-compute

    const int tid = threadIdx.x;
    const int cnt = g_fbcount;
    const int nunits = ((cnt + 127) >> 7) << 2;          // 4 code-quarters per tile

    for (int u = blockIdx.x; u < nunits; u += gridDim.x) {
        const int t = u >> 2, cq = u & 3;
        __syncthreads();
        if (tid < 128) {
            const int li = t * 128 + tid;
            pl[tid] = (li < cnt) ? g_fblist[li] : g_fblist[0];
        }
        __syncthreads();
        {
            const int i = tid & 127;
            const int p = pl[i];
#pragma unroll 4
            for (int j = 0; j < 64; j++) {
                const int d = (tid >> 7) + j * 2;
                xs[d * 128 + i] = g_xT[(size_t)d * NPIX + p];
            }
        }
        __syncthreads();

        const int m0 = (tid >> 4) * 8;
        const int n0 = (tid & 15) * 8;
        const int lr = tid >> 4;
        const int lc = (tid & 15) * 8;

        float minv[8]; int mini[8];
#pragma unroll
        for (int i = 0; i < 8; i++) { minv[i] = 3.4e38f; mini[i] = 0; }

        for (int nt = 0; nt < 2; nt++) {
            const int kb = cq * 256 + nt * 128;
            float acc[8][8];
#pragma unroll
            for (int i = 0; i < 8; i++)
#pragma unroll
                for (int j = 0; j < 8; j++) acc[i][j] = 0.f;

            for (int ks = 0; ks < 8; ks++) {
                const int r = ks * 16 + lr;
                __syncthreads();
                *(float4*)&bs[lr * 128 + lc]     = *(const float4*)&g_eT[r * 1024 + kb + lc];
                *(float4*)&bs[lr * 128 + lc + 4] = *(const float4*)&g_eT[r * 1024 + kb + lc + 4];
                __syncthreads();
#pragma unroll
                for (int kk = 0; kk < 16; kk++) {
                    const int dd = ks * 16 + kk;
                    float4 a0 = *(float4*)&xs[dd * 128 + m0];
                    float4 a1 = *(float4*)&xs[dd * 128 + m0 + 4];
                    float4 b0 = *(float4*)&bs[kk * 128 + n0];
                    float4 b1 = *(float4*)&bs[kk * 128 + n0 + 4];
                    float a[8] = {a0.x, a0.y, a0.z, a0.w, a1.x, a1.y, a1.z, a1.w};
                    float bb[8] = {b0.x, b0.y, b0.z, b0.w, b1.x, b1.y, b1.z, b1.w};
#pragma unroll
                    for (int i = 0; i < 8; i++)
#pragma unroll
                        for (int j = 0; j < 8; j++) acc[i][j] = fmaf(a[i], bb[j], acc[i][j]);
                }
            }
#pragma unroll
            for (int j = 0; j < 8; j++) {
                const float en = g_enorm[kb + n0 + j];
#pragma unroll
                for (int i = 0; i < 8; i++) {
                    float s = fmaf(-2.f, acc[i][j], en);
                    if (s < minv[i]) { minv[i] = s; mini[i] = kb + n0 + j; }
                }
            }
        }
        __syncthreads();  // xs dead -> red aliases
#pragma unroll
        for (int i = 0; i < 8; i++) {
            unsigned int fb = __float_as_uint(minv[i]);
            fb = (fb & 0x80000000u) ? ~fb : (fb | 0x80000000u);
            red[(m0 + i) * 16 + (tid & 15)] = ((unsigned long long)fb << 32) | (unsigned int)mini[i];
        }
        __syncthreads();
        if (tid < 128) {
            unsigned long long m = red[tid * 16];
#pragma unroll
            for (int q = 1; q < 16; q++) {
                unsigned long long v = red[tid * 16 + q];
                if (v < m) m = v;
            }
            atomicMin(&g_fbkey[pl[tid]], m);
        }
    }
}

// ---------------- fbfix: decode combined keys ----------------
__global__ void fbfix_kernel() {
    const int cnt = g_fbcount;
    for (int i = blockIdx.x * blockDim.x + threadIdx.x; i < cnt; i += gridDim.x * blockDim.x) {
        const int p = g_fblist[i];
        const unsigned long long k = g_fbkey[p];
        const unsigned int fb = (unsigned int)(k >> 32);
        const unsigned int bits = (fb & 0x80000000u) ? (fb & 0x7fffffffu) : ~fb;
        g_idx[p] = (int)(k & 0xffffffffu);
        g_score[p] = __uint_as_float(bits);
    }
}

// ---------------- gather: quant write, loss via score identity, counts, idx out ----------------
__global__ __launch_bounds__(256) void gather_kernel(const float* __restrict__ emb,
                                                     float* __restrict__ out) {
    __shared__ float qs[64 * 132];
    __shared__ int sc[64];
    __shared__ float sl[64];
    const int tid = threadIdx.x;
    const int pbase = blockIdx.x * 64;
    const int w = tid >> 5, lane = tid & 31;

#pragma unroll
    for (int it = 0; it < 8; it++) {
        const int pl = w * 8 + it;
        const int c = g_idx[pbase + pl];
        float4 v = *(const float4*)&emb[c * 128 + lane * 4];
        *(float4*)&qs[pl * 132 + lane * 4] = v;
        if (lane == 0) { sc[pl] = c; atomicAdd(&g_counts[c], 1); }
    }
    if (tid < 64) {
        const int p2 = pbase + tid;
        const float xn = g_xnorm[p2];
        sl[tid] = g_score[p2] + xn * xn;   // ||q - x||^2 for this pixel
    }
    __syncthreads();

    const int pl = tid & 63, dg = tid >> 6;
    const int p = pbase + pl;
    const int b = p >> 12, hw = p & 4095;
#pragma unroll
    for (int dd = 0; dd < 32; dd++) {
        const int d = dg * 32 + dd;
        out[Q_OFF + b * (128 * HW) + d * HW + hw] = qs[pl * 132 + d];
    }
    if (tid == 0) {
        float s = 0.f;
        for (int i = 0; i < 64; i++) s += sl[i];
        g_lpart[blockIdx.x] = s;
    }
    if (tid < 64) out[IDX_OFF + pbase + tid] = (float)sc[tid];
}

// ---------------- U precompute GEMM (tile 128M x 64N, 144 blocks) ----------------
__global__ __launch_bounds__(256) void ugemm_kernel() {
    __shared__ float as[16 * 128];
    __shared__ float bs[16 * 64];
    const int tid = threadIdx.x;
    const int mb = blockIdx.y * 128;
    const int nb = blockIdx.x * 64;
    const int m0 = (tid >> 4) * 8;
    const int n0 = (tid & 15) * 4;
    const int lr = tid >> 4;
    const int lc = (tid & 15) * 8;
    const int lc4 = (tid & 15) * 4;

    float acc[8][4];
#pragma unroll
    for (int i = 0; i < 8; i++)
#pragma unroll
        for (int j = 0; j < 4; j++) acc[i][j] = 0.f;

    for (int ks = 0; ks < 8; ks++) {
        const int r = ks * 16 + lr;
        __syncthreads();
        *(float4*)&as[lr * 128 + lc]     = *(const float4*)&g_eT[r * 1024 + mb + lc];
        *(float4*)&as[lr * 128 + lc + 4] = *(const float4*)&g_eT[r * 1024 + mb + lc + 4];
        *(float4*)&bs[lr * 64 + lc4]     = *(const float4*)&g_w2t[r * 1152 + nb + lc4];
        __syncthreads();
#pragma unroll
        for (int kk = 0; kk < 16; kk++) {
            float4 a0 = *(float4*)&as[kk * 128 + m0];
            float4 a1 = *(float4*)&as[kk * 128 + m0 + 4];
            float4 b0 = *(float4*)&bs[kk * 64 + n0];
            float a[8] = {a0.x, a0.y, a0.z, a0.w, a1.x, a1.y, a1.z, a1.w};
            float bb[4] = {b0.x, b0.y, b0.z, b0.w};
#pragma unroll
            for (int i = 0; i < 8; i++)
#pragma unroll
                for (int j = 0; j < 4; j++) acc[i][j] = fmaf(a[i], bb[j], acc[i][j]);
        }
    }
#pragma unroll
    for (int i = 0; i < 8; i++) {
        float4 v0;
        v0.x = acc[i][0]; v0.y = acc[i][1]; v0.z = acc[i][2]; v0.w = acc[i][3];
        *(float4*)&g_U[(size_t)(mb + m0 + i) * 1152 + nb + n0] = v0;
    }
}

// ---------------- conv2 via U table ----------------
__global__ __launch_bounds__(256) void conv2_kernel(const float* __restrict__ bias,
                                                    float* __restrict__ out) {
    __shared__ int nid[3][66];
    const int tid = threadIdx.x;
    const int y = blockIdx.x, b = blockIdx.y;
    if (tid < 198) {
        const int r = tid / 66, xi = tid % 66 - 1;
        const int yy = y + r - 1;
        int v = -1;
        if (yy >= 0 && yy < 64 && xi >= 0 && xi < 64) v = g_idx[b * HW + yy * 64 + xi];
        nid[r][tid % 66] = v;
    }
    __syncthreads();

    const int x = tid & 63, og = tid >> 6;
    const int ob = og * 32;
    float acc[32];
#pragma unroll
    for (int u = 0; u < 32; u++) acc[u] = bias[ob + u];

#pragma unroll
    for (int ky = 0; ky < 3; ky++)
#pragma unroll
        for (int kx = 0; kx < 3; kx++) {
            const int c = nid[ky][x + kx];
            if (c >= 0) {
                const float4* Up = (const float4*)&g_U[(size_t)c * 1152 + (ky * 3 + kx) * 128 + ob];
#pragma unroll
                for (int u4 = 0; u4 < 8; u4++) {
                    float4 v = Up[u4];
                    acc[u4 * 4 + 0] += v.x; acc[u4 * 4 + 1] += v.y;
                    acc[u4 * 4 + 2] += v.z; acc[u4 * 4 + 3] += v.w;
                }
            }
        }
    const int base = NV_OFF + b * (128 * HW) + y * 64 + x;
#pragma unroll
    for (int u = 0; u < 32; u++) out[base + (ob + u) * HW] = acc[u];
}

// ---------------- finalize ----------------
__global__ void finalize_kernel(float* __restrict__ out) {
    __shared__ double ds[256];
    __shared__ float hs[256];
    const int t = threadIdx.x;
    double s = 0.0;
    float h = 0.f;
    for (int k = t; k < 1024; k += 256) {
        s += (double)g_lpart[k];
        const float avg = (float)g_counts[k] * (1.0f / 65536.0f);
        h += avg * logf(avg + 1e-10f);
    }
    ds[t] = s; hs[t] = h;
    __syncthreads();
    for (int off = 128; off > 0; off >>= 1) {
        if (t < off) { ds[t] += ds[t + off]; hs[t] += hs[t + off]; }
        __syncthreads();
    }
    if (t == 0) {
        out[0] = (float)(1.25 * ds[0] / 8388608.0);
        out[PERP_OFF] = expf(-hs[0]);
    }
}

// ---------------- launch (screen is 4th: profiled slot) ----------------
extern "C" void kernel_launch(void* const* d_in, const int* in_sizes, int n_in,
                              void* d_out, int out_size) {
    const float* in  = (const float*)d_in[0];
    const float* w1  = (const float*)d_in[1];
    const float* b1  = (const float*)d_in[2];
    const float* emb = (const float*)d_in[3];
    const float* w2  = (const float*)d_in[4];
    const float* b2  = (const float*)d_in[5];
    float* out = (float*)d_out;

    cudaFuncSetAttribute(screen_kernel, cudaFuncAttributeMaxDynamicSharedMemorySize, SCREEN_SMEM);
    cudaFuncSetAttribute(fb_kernel, cudaFuncAttributeMaxDynamicSharedMemorySize, 74240);

    prep_kernel<<<576, 256>>>(emb, w1, w2);
    prep2_kernel<<<1, 256>>>();
    conv1_kernel<<<dim3(32, 16), 256>>>(in, b1);
    screen_kernel<<<2048, 256, SCREEN_SMEM>>>();
    merge_kernel<<<256, 256>>>();
    fb_kernel<<<256, 256, 74240>>>();
    fbfix_kernel<<<64, 256>>>();
    ugemm_kernel<<<dim3(18, 8), 256>>>();
    gather_kernel<<<1024, 256>>>(emb, out);
    conv2_kernel<<<dim3(64, 16), 256>>>(b2, out);
    finalize_kernel<<<1, 256>>>(out);
}

// round 12
// speedup vs baseline: 1.7671x; 1.1849x over previous
#include <cuda_runtime.h>
#include <cuda_fp16.h>
#include <math.h>
#include <stdint.h>

#define NPIX   65536
#define HW     4096

#define Q_OFF    1
#define NV_OFF   8388609
#define PERP_OFF 16777217
#define IDX_OFF  16777218

// ---------------- scratch (static device arrays; no allocations) ----------------
__device__ float g_xT[128 * NPIX];       // conv1 output, transposed [d][p] (32 MB)
__device__ float g_eT[128 * 1024];       // emb transposed [d][k]
__device__ float g_enorm[1024];          // ||e_k||^2
__device__ float g_w1t[128 * 128];
__device__ float g_w2t[128 * 1152];
__device__ __half g_U16[1024 * 1152];    // U table in fp16 (2.25 MB, L2-resident)
__device__ int   g_idx[NPIX];
__device__ int   g_counts[1024];
__device__ float g_lpart[1024];
__device__ float g_xnorm[NPIX];
__device__ float g_score[NPIX];          // chosen-code score (enorm - 2 x.e)
__device__ unsigned long long g_fbkey[NPIX];
__device__ float g_emax;                 // max ||e||
__device__ float g_en2max;               // max ||e||^2
__device__ int   g_fbcount;
__device__ int   g_fblist[NPIX];
__device__ float g_sm1[2 * NPIX];        // per-half packed top-1 (idx in low 10 bits)
__device__ float g_sm2[2 * NPIX];        // per-half packed top-2
__device__ __align__(16) __half g_x16[NPIX * 128];   // x fp16, row-major [p][d]
__device__ __align__(16) __half g_e16[1024 * 128];   // e fp16, row-major [k][d]

// ---------------- warp MMA helpers (baseline PTX, sm_80+) ----------------
__device__ __forceinline__ uint32_t smem_to_u32(const void* p) {
    uint32_t a;
    asm("{ .reg .u64 t; cvta.to.shared.u64 t, %1; cvt.u32.u64 %0, t; }" : "=r"(a) : "l"(p));
    return a;
}
__device__ __forceinline__ void ldsm_x4(uint32_t& r0, uint32_t& r1, uint32_t& r2, uint32_t& r3, uint32_t addr) {
    asm volatile("ldmatrix.sync.aligned.m8n8.x4.shared.b16 {%0,%1,%2,%3}, [%4];"
                 : "=r"(r0), "=r"(r1), "=r"(r2), "=r"(r3) : "r"(addr));
}
__device__ __forceinline__ void mma16816(float* c, const uint32_t* a, const uint32_t* b) {
    asm volatile("mma.sync.aligned.m16n8k16.row.col.f32.f16.f16.f32 "
                 "{%0,%1,%2,%3}, {%4,%5,%6,%7}, {%8,%9}, {%0,%1,%2,%3};"
                 : "+f"(c[0]), "+f"(c[1]), "+f"(c[2]), "+f"(c[3])
                 : "r"(a[0]), "r"(a[1]), "r"(a[2]), "r"(a[3]), "r"(b[0]), "r"(b[1]));
}
__device__ __forceinline__ void cp_async16(uint32_t smem_addr, const void* gptr) {
    asm volatile("cp.async.cg.shared.global [%0], [%1], 16;" :: "r"(smem_addr), "l"(gptr));
}
#define CP_COMMIT() asm volatile("cp.async.commit_group;" ::: "memory")
#define CP_WAIT0()  asm volatile("cp.async.wait_group 0;" ::: "memory")

// ---------------- prep ----------------
__global__ void prep_kernel(const float* __restrict__ emb,
                            const float* __restrict__ w1,
                            const float* __restrict__ w2) {
    int t = blockIdx.x * blockDim.x + threadIdx.x;
    if (t < 131072) {
        int k = t >> 7, d = t & 127;
        float v = emb[t];
        g_eT[d * 1024 + k] = v;
        g_e16[t] = __float2half_rn(v);
    }
    if (t < 16384)  { int d = t >> 7, c = t & 127; g_w1t[c * 128 + d] = w1[t]; }
    if (t < 147456) {
        int o = t / 1152; int r = t - o * 1152; int i = r / 9, j = r - i * 9;
        g_w2t[i * 1152 + j * 128 + o] = w2[t];
    }
    if (t < 1024) {
        const float* e = emb + t * 128;
        float s = 0.f;
        for (int d = 0; d < 128; d++) s = fmaf(e[d], e[d], s);
        g_enorm[t] = s;
        g_counts[t] = 0;
    }
}

__global__ void prep2_kernel() {
    __shared__ float mx[256];
    const int t = threadIdx.x;
    float m = 0.f;
    for (int k = t; k < 1024; k += 256) m = fmaxf(m, g_enorm[k]);
    mx[t] = m;
    __syncthreads();
    for (int off = 128; off > 0; off >>= 1) {
        if (t < off) mx[t] = fmaxf(mx[t], mx[t + off]);
        __syncthreads();
    }
    if (t == 0) { g_en2max = mx[0]; g_emax = sqrtf(mx[0]); g_fbcount = 0; }
}

// ---------------- conv1: cp.async double-buffered SGEMM + fused fp16/norm epilogue ----------------
__global__ __launch_bounds__(256) void conv1_kernel(const float* __restrict__ in,
                                                    const float* __restrict__ bias) {
    __shared__ float as[2][16 * 128];
    __shared__ float bs[2][16 * 128];
    __shared__ float pn[128][17];
    const int tid = threadIdx.x;
    const int b   = blockIdx.y;
    const int hwb = blockIdx.x * 128;
    const int m0  = (tid >> 4) * 8;
    const int n0  = (tid & 15) * 8;
    const int lr  = tid >> 4;
    const int lc  = (tid & 15) * 8;
    const float* B = in + b * (128 * HW);
    const uint32_t as_b = smem_to_u32(as);
    const uint32_t bs_b = smem_to_u32(bs);

    float acc[8][8];
#pragma unroll
    for (int i = 0; i < 8; i++)
#pragma unroll
        for (int j = 0; j < 8; j++) acc[i][j] = 0.f;

    {
        const int c0 = lr;
        cp_async16(as_b + (uint32_t)(lr * 128 + lc) * 4,       &g_w1t[c0 * 128 + lc]);
        cp_async16(as_b + (uint32_t)(lr * 128 + lc + 4) * 4,   &g_w1t[c0 * 128 + lc + 4]);
        cp_async16(bs_b + (uint32_t)(lr * 128 + lc) * 4,       &B[c0 * HW + hwb + lc]);
        cp_async16(bs_b + (uint32_t)(lr * 128 + lc + 4) * 4,   &B[c0 * HW + hwb + lc + 4]);
        CP_COMMIT();
    }
    CP_WAIT0();
    __syncthreads();

    for (int ks = 0; ks < 8; ks++) {
        const int cur = ks & 1;
        if (ks < 7) {
            const int nb = (ks + 1) & 1;
            const int c0 = (ks + 1) * 16 + lr;
            const uint32_t off = (uint32_t)(nb * 2048 + lr * 128 + lc) * 4;
            cp_async16(as_b + off,      &g_w1t[c0 * 128 + lc]);
            cp_async16(as_b + off + 16, &g_w1t[c0 * 128 + lc + 4]);
            cp_async16(bs_b + off,      &B[c0 * HW + hwb + lc]);
            cp_async16(bs_b + off + 16, &B[c0 * HW + hwb + lc + 4]);
            CP_COMMIT();
        }
#pragma unroll
        for (int kk = 0; kk < 16; kk++) {
            float4 a0 = *(float4*)&as[cur][kk * 128 + m0];
            float4 a1 = *(float4*)&as[cur][kk * 128 + m0 + 4];
            float4 b0 = *(float4*)&bs[cur][kk * 128 + n0];
            float4 b1 = *(float4*)&bs[cur][kk * 128 + n0 + 4];
            float a[8] = {a0.x, a0.y, a0.z, a0.w, a1.x, a1.y, a1.z, a1.w};
            float bb[8] = {b0.x, b0.y, b0.z, b0.w, b1.x, b1.y, b1.z, b1.w};
#pragma unroll
            for (int i = 0; i < 8; i++)
#pragma unroll
                for (int j = 0; j < 8; j++) acc[i][j] = fmaf(a[i], bb[j], acc[i][j]);
        }
        CP_WAIT0();
        __syncthreads();
    }
#pragma unroll
    for (int i = 0; i < 8; i++) {
        const float bv = bias[m0 + i];
#pragma unroll
        for (int j = 0; j < 8; j++) acc[i][j] += bv;
    }
#pragma unroll
    for (int i = 0; i < 8; i++) {
        float4 v0, v1;
        v0.x = acc[i][0]; v0.y = acc[i][1]; v0.z = acc[i][2]; v0.w = acc[i][3];
        v1.x = acc[i][4]; v1.y = acc[i][5]; v1.z = acc[i][6]; v1.w = acc[i][7];
        float* dst = &g_xT[(size_t)(m0 + i) * NPIX + b * HW + hwb + n0];
        *(float4*)dst = v0;
        *(float4*)(dst + 4) = v1;
    }
#pragma unroll
    for (int j = 0; j < 8; j++) {
        const int p = b * HW + hwb + n0 + j;
        __half h[8];
#pragma unroll
        for (int i = 0; i < 8; i++) h[i] = __float2half_rn(acc[i][j]);
        *(uint4*)&g_x16[(size_t)p * 128 + m0] = *(uint4*)h;
    }
#pragma unroll
    for (int j = 0; j < 8; j++) {
        float s = 0.f;
#pragma unroll
        for (int i = 0; i < 8; i++) s = fmaf(acc[i][j], acc[i][j], s);
        pn[n0 + j][tid >> 4] = s;
    }
    __syncthreads();
    if (tid < 128) {
        float s = 0.f;
#pragma unroll
        for (int g = 0; g < 16; g++) s += pn[tid][g];
        g_xnorm[b * HW + hwb + tid] = sqrtf(s);
    }
}

// ---------------- screen: fp16 mma.sync, packed-index top-2, 64px x 512 codes ----------------
#define PITCH  136
#define ES0    17408
#define ES1    52224
#define EN_OFF 87040
#define SCREEN_SMEM 89088

__global__ __launch_bounds__(256, 2) void screen_kernel() {
    extern __shared__ char smc[];
    const uint32_t smb = smem_to_u32(smc);
    const int tid = threadIdx.x;
    const int lane = tid & 31, wid = tid >> 5;
    const int wm = wid >> 2, wn = wid & 3;       // 2 x 4 warp grid; warp tile 32 x 32
    const int pt = blockIdx.x >> 1;
    const int ch = blockIdx.x & 1;
    const int pbase = pt * 64;

#pragma unroll
    for (int j = 0; j < 4; j++) {
        const int id = j * 256 + tid, r = id >> 4, c = id & 15;
        cp_async16(smb + (uint32_t)(r * PITCH + c * 8) * 2,
                   (const char*)g_x16 + (size_t)(pbase + r) * 256 + c * 16);
    }
#pragma unroll
    for (int j = 0; j < 8; j++) {
        const int id = j * 256 + tid, r = id >> 4, c = id & 15;
        cp_async16(smb + ES0 + (uint32_t)(r * PITCH + c * 8) * 2,
                   (const char*)g_e16 + (size_t)(ch * 4) * 32768 + r * 256 + c * 16);
    }
    if (tid < 128) *(float4*)(smc + EN_OFF + tid * 16) = *(const float4*)&g_enorm[ch * 512 + tid * 4];
    CP_COMMIT();
    CP_WAIT0();
    __syncthreads();

    const float* ensm = (const float*)(smc + EN_OFF);
    const float FINF = __uint_as_float(0x7F800000u);
    float mn1[4], mn2[4];
#pragma unroll
    for (int s = 0; s < 4; s++) { mn1[s] = FINF; mn2[s] = FINF; }

    const uint32_t a_row = (uint32_t)(wm * 32 + (lane & 15));
    const uint32_t a_koff = (uint32_t)((lane >> 4) << 3);
    const uint32_t b_row = (uint32_t)(wn * 32 + ((lane >> 4) << 3) + (lane & 7));
    const uint32_t b_koff = (uint32_t)(((lane >> 3) & 1) << 3);

    for (int nt = 0; nt < 4; nt++) {
        const int ebase = (nt & 1) ? ES1 : ES0;
        float acc[2][4][4];
#pragma unroll
        for (int mt = 0; mt < 2; mt++)
#pragma unroll
            for (int ntl = 0; ntl < 4; ntl++)
#pragma unroll
                for (int c = 0; c < 4; c++) acc[mt][ntl][c] = 0.f;

        if (nt < 3) {
            const char* src = (const char*)g_e16 + (size_t)(ch * 4 + nt + 1) * 32768;
            const uint32_t dst = smb + ((nt & 1) ? ES0 : ES1);
#pragma unroll
            for (int j = 0; j < 8; j++) {
                const int id = j * 256 + tid, r = id >> 4, c = id & 15;
                cp_async16(dst + (uint32_t)(r * PITCH + c * 8) * 2, src + r * 256 + c * 16);
            }
            CP_COMMIT();
        }

        uint32_t a[2][2][4], b[2][4][2];
        {
#pragma unroll
            for (int mt = 0; mt < 2; mt++) {
                const uint32_t addr = smb + ((a_row + mt * 16) * PITCH + a_koff) * 2;
                ldsm_x4(a[0][mt][0], a[0][mt][1], a[0][mt][2], a[0][mt][3], addr);
            }
#pragma unroll
            for (int nb = 0; nb < 2; nb++) {
                uint32_t r0, r1, r2, r3;
                const uint32_t addr = smb + ebase + ((b_row + nb * 16) * PITCH + b_koff) * 2;
                ldsm_x4(r0, r1, r2, r3, addr);
                b[0][nb * 2][0] = r0; b[0][nb * 2][1] = r1;
                b[0][nb * 2 + 1][0] = r2; b[0][nb * 2 + 1][1] = r3;
            }
        }
#pragma unroll
        for (int kk = 0; kk < 8; kk++) {
            const int cur = kk & 1, nxt = cur ^ 1;
            if (kk < 7) {
                const int k2 = (kk + 1) * 16;
#pragma unroll
                for (int mt = 0; mt < 2; mt++) {
                    const uint32_t addr = smb + ((a_row + mt * 16) * PITCH + k2 + a_koff) * 2;
                    ldsm_x4(a[nxt][mt][0], a[nxt][mt][1], a[nxt][mt][2], a[nxt][mt][3], addr);
                }
#pragma unroll
                for (int nb = 0; nb < 2; nb++) {
                    uint32_t r0, r1, r2, r3;
                    const uint32_t addr = smb + ebase + ((b_row + nb * 16) * PITCH + k2 + b_koff) * 2;
                    ldsm_x4(r0, r1, r2, r3, addr);
                    b[nxt][nb * 2][0] = r0; b[nxt][nb * 2][1] = r1;
                    b[nxt][nb * 2 + 1][0] = r2; b[nxt][nb * 2 + 1][1] = r3;
                }
            }
#pragma unroll
            for (int mt = 0; mt < 2; mt++)
#pragma unroll
                for (int ntl = 0; ntl < 4; ntl++) mma16816(acc[mt][ntl], a[cur][mt], b[cur][ntl]);
        }
        // packed-index branchless top-2: score low 10 mantissa bits carry col (0..511)
#pragma unroll
        for (int mt = 0; mt < 2; mt++)
#pragma unroll
            for (int c = 0; c < 4; c++) {
                const int slot = mt * 2 + (c >> 1);
#pragma unroll
                for (int ntl = 0; ntl < 4; ntl++) {
                    const int col = nt * 128 + wn * 32 + ntl * 8 + ((lane & 3) << 1) + (c & 1);
                    const float s = fmaf(-2.f, acc[mt][ntl][c], ensm[col]);
                    const float sp = __uint_as_float((__float_as_uint(s) & 0xFFFFFC00u) | (uint32_t)col);
                    mn2[slot] = fminf(mn2[slot], fmaxf(mn1[slot], sp));
                    mn1[slot] = fminf(mn1[slot], sp);
                }
            }
        if (nt < 3) CP_WAIT0();
        __syncthreads();
    }

    // in-warp merge across the 4 lanes sharing each row (lane&3 partitions cols)
#pragma unroll
    for (int s = 0; s < 4; s++) {
#pragma unroll
        for (int m = 1; m <= 2; m <<= 1) {
            const float o1 = __shfl_xor_sync(0xffffffffu, mn1[s], m);
            const float o2 = __shfl_xor_sync(0xffffffffu, mn2[s], m);
            const float hi = fmaxf(mn1[s], o1);
            mn1[s] = fminf(mn1[s], o1);
            mn2[s] = fminf(fminf(mn2[s], o2), hi);
        }
    }
    // cross-warp merge via smem (x region dead: 2 KB < 17 KB)
    float* f1 = (float*)smc;
    float* f2 = (float*)(smc + 1024);
    if ((lane & 3) == 0) {
#pragma unroll
        for (int s = 0; s < 4; s++) {
            const int row = wm * 32 + (s >> 1) * 16 + (s & 1) * 8 + (lane >> 2);
            f1[row * 4 + wn] = mn1[s];
            f2[row * 4 + wn] = mn2[s];
        }
    }
    __syncthreads();
    if (tid < 64) {
        float m1 = f1[tid * 4], m2 = f2[tid * 4];
#pragma unroll
        for (int w = 1; w < 4; w++) {
            const float o1 = f1[tid * 4 + w], o2 = f2[tid * 4 + w];
            const float hi = fmaxf(m1, o1);
            m1 = fminf(m1, o1);
            m2 = fminf(fminf(m2, o2), hi);
        }
        const int p = pbase + tid;
        g_sm1[ch * NPIX + p] = m1;
        g_sm2[ch * NPIX + p] = m2;
    }
}

// ---------------- merge halves + margin test (decode packed indices) ----------------
__global__ __launch_bounds__(256) void merge_kernel() {
    const int p = blockIdx.x * blockDim.x + threadIdx.x;
    const float a1 = g_sm1[p], b1 = g_sm1[NPIX + p];
    const float a2 = g_sm2[p], b2 = g_sm2[NPIX + p];
    float m1, m2; int i1;
    if (a1 <= b1) { m1 = a1; i1 = (int)(__float_as_uint(a1) & 1023u); m2 = fminf(a2, b1); }
    else { m1 = b1; i1 = 512 + (int)(__float_as_uint(b1) & 1023u); m2 = fminf(b2, a1); }
    g_idx[p] = i1;
    g_score[p] = __uint_as_float(__float_as_uint(m1) & 0xFFFFFC00u);
    const float xn = g_xnorm[p];
    // fp16-dot margin + packed-mantissa perturbation margin
    const float thresh = fmaf(5.0e-3f * g_emax, xn, fmaf(2.5e-4f, g_en2max, 1e-5f));
    if (m2 - m1 <= thresh) {
        g_fbkey[p] = 0xFFFFFFFFFFFFFFFFull;
        const int pos = atomicAdd(&g_fbcount, 1);
        g_fblist[pos] = p;
    }
}

// ---------------- full fallback: 4-way code-split exact fp32 argmin ----------------
__global__ __launch_bounds__(256) void fb_kernel() {
    extern __shared__ float sm[];
    float* xs = sm;                                      // [128d][128px] 64 KB
    float* bs = sm + 16384;
    int*   pl = (int*)(sm + 18432);
    unsigned long long* red = (unsigned long long*)sm;   // aliases xs post-compute

    const int tid = threadIdx.x;
    const int cnt = g_fbcount;
    const int nunits = ((cnt + 127) >> 7) << 2;          // 4 code-quarters per tile

    for (int u = blockIdx.x; u < nunits; u += gridDim.x) {
        const int t = u >> 2, cq = u & 3;
        __syncthreads();
        if (tid < 128) {
            const int li = t * 128 + tid;
            pl[tid] = (li < cnt) ? g_fblist[li] : g_fblist[0];
        }
        __syncthreads();
        {
            const int i = tid & 127;
            const int p = pl[i];
#pragma unroll 4
            for (int j = 0; j < 64; j++) {
                const int d = (tid >> 7) + j * 2;
                xs[d * 128 + i] = g_xT[(size_t)d * NPIX + p];
            }
        }
        __syncthreads();

        const int m0 = (tid >> 4) * 8;
        const int n0 = (tid & 15) * 8;
        const int lr = tid >> 4;
        const int lc = (tid & 15) * 8;

        float minv[8]; int mini[8];
#pragma unroll
        for (int i = 0; i < 8; i++) { minv[i] = 3.4e38f; mini[i] = 0; }

        for (int nt = 0; nt < 2; nt++) {
            const int kb = cq * 256 + nt * 128;
            float acc[8][8];
#pragma unroll
            for (int i = 0; i < 8; i++)
#pragma unroll
                for (int j = 0; j < 8; j++) acc[i][j] = 0.f;

            for (int ks = 0; ks < 8; ks++) {
                const int r = ks * 16 + lr;
                __syncthreads();
                *(float4*)&bs[lr * 128 + lc]     = *(const float4*)&g_eT[r * 1024 + kb + lc];
                *(float4*)&bs[lr * 128 + lc + 4] = *(const float4*)&g_eT[r * 1024 + kb + lc + 4];
                __syncthreads();
#pragma unroll
                for (int kk = 0; kk < 16; kk++) {
                    const int dd = ks * 16 + kk;
                    float4 a0 = *(float4*)&xs[dd * 128 + m0];
                    float4 a1 = *(float4*)&xs[dd * 128 + m0 + 4];
                    float4 b0 = *(float4*)&bs[kk * 128 + n0];
                    float4 b1 = *(float4*)&bs[kk * 128 + n0 + 4];
                    float a[8] = {a0.x, a0.y, a0.z, a0.w, a1.x, a1.y, a1.z, a1.w};
                    float bb[8] = {b0.x, b0.y, b0.z, b0.w, b1.x, b1.y, b1.z, b1.w};
#pragma unroll
                    for (int i = 0; i < 8; i++)
#pragma unroll
                        for (int j = 0; j < 8; j++) acc[i][j] = fmaf(a[i], bb[j], acc[i][j]);
                }
            }
#pragma unroll
            for (int j = 0; j < 8; j++) {
                const float en = g_enorm[kb + n0 + j];
#pragma unroll
                for (int i = 0; i < 8; i++) {
                    float s = fmaf(-2.f, acc[i][j], en);
                    if (s < minv[i]) { minv[i] = s; mini[i] = kb + n0 + j; }
                }
            }
        }
        __syncthreads();  // xs dead -> red aliases
#pragma unroll
        for (int i = 0; i < 8; i++) {
            unsigned int fb = __float_as_uint(minv[i]);
            fb = (fb & 0x80000000u) ? ~fb : (fb | 0x80000000u);
            red[(m0 + i) * 16 + (tid & 15)] = ((unsigned long long)fb << 32) | (unsigned int)mini[i];
        }
        __syncthreads();
        if (tid < 128) {
            unsigned long long m = red[tid * 16];
#pragma unroll
            for (int q = 1; q < 16; q++) {
                unsigned long long v = red[tid * 16 + q];
                if (v < m) m = v;
            }
            atomicMin(&g_fbkey[pl[tid]], m);
        }
    }
}

// ---------------- fbfix: decode combined keys ----------------
__global__ void fbfix_kernel() {
    const int cnt = g_fbcount;
    for (int i = blockIdx.x * blockDim.x + threadIdx.x; i < cnt; i += gridDim.x * blockDim.x) {
        const int p = g_fblist[i];
        const unsigned long long k = g_fbkey[p];
        const unsigned int fb = (unsigned int)(k >> 32);
        const unsigned int bits = (fb & 0x80000000u) ? (fb & 0x7fffffffu) : ~fb;
        g_idx[p] = (int)(k & 0xffffffffu);
        g_score[p] = __uint_as_float(bits);
    }
}

// ---------------- gather: quant write, loss via score identity, counts, idx out ----------------
__global__ __launch_bounds__(256) void gather_kernel(const float* __restrict__ emb,
                                                     float* __restrict__ out) {
    __shared__ float qs[64 * 132];
    __shared__ int sc[64];
    __shared__ float sl[64];
    const int tid = threadIdx.x;
    const int pbase = blockIdx.x * 64;
    const int w = tid >> 5, lane = tid & 31;

#pragma unroll
    for (int it = 0; it < 8; it++) {
        const int pl = w * 8 + it;
        const int c = g_idx[pbase + pl];
        float4 v = *(const float4*)&emb[c * 128 + lane * 4];
        *(float4*)&qs[pl * 132 + lane * 4] = v;
        if (lane == 0) { sc[pl] = c; atomicAdd(&g_counts[c], 1); }
    }
    if (tid < 64) {
        const int p2 = pbase + tid;
        const float xn = g_xnorm[p2];
        sl[tid] = g_score[p2] + xn * xn;
    }
    __syncthreads();

    const int pl = tid & 63, dg = tid >> 6;
    const int p = pbase + pl;
    const int b = p >> 12, hw = p & 4095;
#pragma unroll
    for (int dd = 0; dd < 32; dd++) {
        const int d = dg * 32 + dd;
        out[Q_OFF + b * (128 * HW) + d * HW + hw] = qs[pl * 132 + d];
    }
    if (tid == 0) {
        float s = 0.f;
        for (int i = 0; i < 64; i++) s += sl[i];
        g_lpart[blockIdx.x] = s;
    }
    if (tid < 64) out[IDX_OFF + pbase + tid] = (float)sc[tid];
}

// ---------------- U precompute GEMM (fp16 output, tile 128M x 64N) ----------------
__global__ __launch_bounds__(256) void ugemm_kernel() {
    __shared__ float as[16 * 128];
    __shared__ float bs[16 * 64];
    const int tid = threadIdx.x;
    const int mb = blockIdx.y * 128;
    const int nb = blockIdx.x * 64;
    const int m0 = (tid >> 4) * 8;
    const int n0 = (tid & 15) * 4;
    const int lr = tid >> 4;
    const int lc = (tid & 15) * 8;
    const int lc4 = (tid & 15) * 4;

    float acc[8][4];
#pragma unroll
    for (int i = 0; i < 8; i++)
#pragma unroll
        for (int j = 0; j < 4; j++) acc[i][j] = 0.f;

    for (int ks = 0; ks < 8; ks++) {
        const int r = ks * 16 + lr;
        __syncthreads();
        *(float4*)&as[lr * 128 + lc]     = *(const float4*)&g_eT[r * 1024 + mb + lc];
        *(float4*)&as[lr * 128 + lc + 4] = *(const float4*)&g_eT[r * 1024 + mb + lc + 4];
        *(float4*)&bs[lr * 64 + lc4]     = *(const float4*)&g_w2t[r * 1152 + nb + lc4];
        __syncthreads();
#pragma unroll
        for (int kk = 0; kk < 16; kk++) {
            float4 a0 = *(float4*)&as[kk * 128 + m0];
            float4 a1 = *(float4*)&as[kk * 128 + m0 + 4];
            float4 b0 = *(float4*)&bs[kk * 64 + n0];
            float a[8] = {a0.x, a0.y, a0.z, a0.w, a1.x, a1.y, a1.z, a1.w};
            float bb[4] = {b0.x, b0.y, b0.z, b0.w};
#pragma unroll
            for (int i = 0; i < 8; i++)
#pragma unroll
                for (int j = 0; j < 4; j++) acc[i][j] = fmaf(a[i], bb[j], acc[i][j]);
        }
    }
#pragma unroll
    for (int i = 0; i < 8; i++) {
        union { __half2 h[2]; uint2 u; } st;
        st.h[0] = __floats2half2_rn(acc[i][0], acc[i][1]);
        st.h[1] = __floats2half2_rn(acc[i][2], acc[i][3]);
        *(uint2*)&g_U16[(size_t)(mb + m0 + i) * 1152 + nb + n0] = st.u;
    }
}

// ---------------- conv2 via fp16 U table ----------------
__global__ __launch_bounds__(256) void conv2_kernel(const float* __restrict__ bias,
                                                    float* __restrict__ out) {
    __shared__ int nid[3][66];
    const int tid = threadIdx.x;
    const int y = blockIdx.x, b = blockIdx.y;
    if (tid < 198) {
        const int r = tid / 66, xi = tid % 66 - 1;
        const int yy = y + r - 1;
        int v = -1;
        if (yy >= 0 && yy < 64 && xi >= 0 && xi < 64) v = g_idx[b * HW + yy * 64 + xi];
        nid[r][tid % 66] = v;
    }
    __syncthreads();

    const int x = tid & 63, og = tid >> 6;
    const int ob = og * 32;
    float acc[32];
#pragma unroll
    for (int u = 0; u < 32; u++) acc[u] = bias[ob + u];

#pragma unroll
    for (int ky = 0; ky < 3; ky++)
#pragma unroll
        for (int kx = 0; kx < 3; kx++) {
            const int c = nid[ky][x + kx];
            if (c >= 0) {
                const uint4* Up = (const uint4*)&g_U16[(size_t)c * 1152 + (ky * 3 + kx) * 128 + ob];
#pragma unroll
                for (int q4 = 0; q4 < 4; q4++) {
                    uint4 v = Up[q4];
                    const __half2* h2 = (const __half2*)&v;
#pragma unroll
                    for (int t = 0; t < 4; t++) {
                        float2 f = __half22float2(h2[t]);
                        acc[q4 * 8 + t * 2]     += f.x;
                        acc[q4 * 8 + t * 2 + 1] += f.y;
                    }
                }
            }
        }
    const int base = NV_OFF + b * (128 * HW) + y * 64 + x;
#pragma unroll
    for (int u = 0; u < 32; u++) out[base + (ob + u) * HW] = acc[u];
}

// ---------------- finalize ----------------
__global__ void finalize_kernel(float* __restrict__ out) {
    __shared__ double ds[256];
    __shared__ float hs[256];
    const int t = threadIdx.x;
    double s = 0.0;
    float h = 0.f;
    for (int k = t; k < 1024; k += 256) {
        s += (double)g_lpart[k];
        const float avg = (float)g_counts[k] * (1.0f / 65536.0f);
        h += avg * logf(avg + 1e-10f);
    }
    ds[t] = s; hs[t] = h;
    __syncthreads();
    for (int off = 128; off > 0; off >>= 1) {
        if (t < off) { ds[t] += ds[t + off]; hs[t] += hs[t + off]; }
        __syncthreads();
    }
    if (t == 0) {
        out[0] = (float)(1.25 * ds[0] / 8388608.0);
        out[PERP_OFF] = expf(-hs[0]);
    }
}

// ---------------- launch (screen is 4th: profiled slot) ----------------
extern "C" void kernel_launch(void* const* d_in, const int* in_sizes, int n_in,
                              void* d_out, int out_size) {
    const float* in  = (const float*)d_in[0];
    const float* w1  = (const float*)d_in[1];
    const float* b1  = (const float*)d_in[2];
    const float* emb = (const float*)d_in[3];
    const float* w2  = (const float*)d_in[4];
    const float* b2  = (const float*)d_in[5];
    float* out = (float*)d_out;

    cudaFuncSetAttribute(screen_kernel, cudaFuncAttributeMaxDynamicSharedMemorySize, SCREEN_SMEM);
    cudaFuncSetAttribute(fb_kernel, cudaFuncAttributeMaxDynamicSharedMemorySize, 74240);

    prep_kernel<<<576, 256>>>(emb, w1, w2);
    prep2_kernel<<<1, 256>>>();
    conv1_kernel<<<dim3(32, 16), 256>>>(in, b1);
    screen_kernel<<<2048, 256, SCREEN_SMEM>>>();
    merge_kernel<<<256, 256>>>();
    fb_kernel<<<256, 256, 74240>>>();
    fbfix_kernel<<<64, 256>>>();
    ugemm_kernel<<<dim3(18, 8), 256>>>();
    gather_kernel<<<1024, 256>>>(emb, out);
    conv2_kernel<<<dim3(64, 16), 256>>>(b2, out);
    finalize_kernel<<<1, 256>>>(out);
}